// round 9
// baseline (speedup 1.0000x reference)
#include <cuda_runtime.h>
#include <cuda_bf16.h>
#include <cstdint>

// ---------------------------------------------------------------------------
// Problem shape (fixed by dataset): N=50000, E=1.6M, D=128, A=4, H=128
// ---------------------------------------------------------------------------
#define NMAX 50048          // 782 tiles of 64
#define EMAX 1700000
#define DDIM 128

__device__ __nv_bfloat16 g_P[(size_t)NMAX * DDIM];      // bf16 activations (pre-edge)
__device__ __nv_bfloat16 g_poolb[(size_t)NMAX * DDIM];  // bf16 pooled output
__device__ float g_x1  [(size_t)NMAX * DDIM];           // fp32 residual stream
__device__ __nv_bfloat16 g_Wt[4 * 128 * 128];           // transposed bf16 weights
__device__ int   g_eidx[EMAX];                          // edge neighbor index
__device__ uint2 g_eadd[EMAX];                          // edge add-info, bf16 x4
__device__ int   g_start[NMAX + 1];                     // CSR segment starts

// ---------------------------------------------------------------------------
// helpers
// ---------------------------------------------------------------------------
__device__ __forceinline__ uint32_t smem_u32(const void* p) {
    uint32_t a;
    asm("{ .reg .u64 t; cvta.to.shared.u64 t, %1; cvt.u32.u64 %0, t; }"
        : "=r"(a) : "l"(p));
    return a;
}
__device__ __forceinline__ void ldsm_x4(uint32_t& r0, uint32_t& r1,
                                        uint32_t& r2, uint32_t& r3, uint32_t a) {
    asm volatile("ldmatrix.sync.aligned.m8n8.x4.shared.b16 {%0,%1,%2,%3}, [%4];"
                 : "=r"(r0), "=r"(r1), "=r"(r2), "=r"(r3) : "r"(a));
}
__device__ __forceinline__ void ldsm_x2(uint32_t& r0, uint32_t& r1, uint32_t a) {
    asm volatile("ldmatrix.sync.aligned.m8n8.x2.shared.b16 {%0,%1}, [%2];"
                 : "=r"(r0), "=r"(r1) : "r"(a));
}
__device__ __forceinline__ void mma_bf16(float* c, const uint32_t* a, const uint32_t* b) {
    asm volatile(
        "mma.sync.aligned.m16n8k16.row.col.f32.bf16.bf16.f32 "
        "{%0,%1,%2,%3}, {%4,%5,%6,%7}, {%8,%9}, {%0,%1,%2,%3};"
        : "+f"(c[0]), "+f"(c[1]), "+f"(c[2]), "+f"(c[3])
        : "r"(a[0]), "r"(a[1]), "r"(a[2]), "r"(a[3]), "r"(b[0]), "r"(b[1]));
}

// ---------------------------------------------------------------------------
// Tiling constants: CTA = 64 rows x 128 cols, 8 warps (2 m x 4 n), K=128
// ---------------------------------------------------------------------------
#define BSTR 136                              // bf16 elems per smem row (pad 8)
static constexpr int SMEM_A  = 64 * BSTR * 2;    // 17408
static constexpr int SMEM_B  = 128 * BSTR * 2;   // 34816
static constexpr int SMEM_PF = SMEM_A + SMEM_B;          // 52224 (pre/fin)
static constexpr int SMEM_MID = SMEM_A + 2 * SMEM_B;     // 87040 (mid)

// A tile fill: 64x128 fp32 -> bf16 smem
__device__ __forceinline__ void fill_A(char* smem, const float* __restrict__ A,
                                       int tile0, int M, int tid) {
#pragma unroll
    for (int it = 0; it < 8; it++) {
        int p = it * 256 + tid;               // 0..2047
        int r = p >> 5, c = p & 31;
        int gr = tile0 + r;
        float4 v = make_float4(0.f, 0.f, 0.f, 0.f);
        if (gr < M) v = __ldg(reinterpret_cast<const float4*>(A + (size_t)gr * 128) + c);
        __nv_bfloat162 lo = __floats2bfloat162_rn(v.x, v.y);
        __nv_bfloat162 hi = __floats2bfloat162_rn(v.z, v.w);
        uint2 o = make_uint2(*reinterpret_cast<uint32_t*>(&lo),
                             *reinterpret_cast<uint32_t*>(&hi));
        *reinterpret_cast<uint2*>(smem + r * (BSTR * 2) + c * 8) = o;
    }
}
// A tile fill from bf16 source (straight copy)
__device__ __forceinline__ void fill_Abf(char* smem, const __nv_bfloat16* __restrict__ A,
                                         int tile0, int M, int tid) {
    const uint4* src = reinterpret_cast<const uint4*>(A + (size_t)tile0 * 128);
#pragma unroll
    for (int it = 0; it < 4; it++) {
        int p = it * 256 + tid;               // 0..1023
        int r = p >> 4, c = p & 15;
        uint4 v = make_uint4(0, 0, 0, 0);
        if (tile0 + r < M) v = __ldg(src + p);
        *reinterpret_cast<uint4*>(smem + r * (BSTR * 2) + c * 16) = v;
    }
}
// B tile fill: 128x128 bf16 (pre-transposed) -> smem, uint4 copies
__device__ __forceinline__ void fill_B(char* dst, const __nv_bfloat16* __restrict__ Wt,
                                       int tid) {
    const uint4* src = reinterpret_cast<const uint4*>(Wt);
#pragma unroll
    for (int it = 0; it < 8; it++) {
        int p = it * 256 + tid;               // 0..2047
        int n = p >> 4, c = p & 15;
        *reinterpret_cast<uint4*>(dst + n * (BSTR * 2) + c * 16) = src[p];
    }
}
// MMA core: acc[2][4][4] over 64x128 tile
__device__ __forceinline__ void mma_tile(uint32_t sA, uint32_t sB,
                                         float acc[2][4][4], int lane,
                                         int wm, int wn) {
    int aRow = wm * 32 + (lane & 15);
    int aCol = (lane >> 4) * 8;
    int bRow = wn * 32 + (lane & 7);
    int bCol = ((lane >> 3) & 1) * 8;
#pragma unroll
    for (int k = 0; k < 8; k++) {
        uint32_t a[2][4], b[4][2];
#pragma unroll
        for (int mt = 0; mt < 2; mt++)
            ldsm_x4(a[mt][0], a[mt][1], a[mt][2], a[mt][3],
                    sA + (aRow + mt * 16) * (BSTR * 2) + (k * 16 + aCol) * 2);
#pragma unroll
        for (int nt = 0; nt < 4; nt++)
            ldsm_x2(b[nt][0], b[nt][1],
                    sB + (bRow + nt * 8) * (BSTR * 2) + (k * 16 + bCol) * 2);
#pragma unroll
        for (int mt = 0; mt < 2; mt++)
#pragma unroll
            for (int nt = 0; nt < 4; nt++)
                mma_bf16(acc[mt][nt], a[mt], b[nt]);
    }
}

// ---------------------------------------------------------------------------
// prep: Wt[w][n][k] = bf16(W_w[k][n])
// ---------------------------------------------------------------------------
__global__ void __launch_bounds__(256)
prep_w(const float* __restrict__ W0, const float* __restrict__ W1,
       const float* __restrict__ W2, const float* __restrict__ W3,
       __nv_bfloat16* __restrict__ Wt)
{
    const float* Ws[4] = {W0, W1, W2, W3};
    const float* W = Ws[blockIdx.y];
    __nv_bfloat16* dst = Wt + (size_t)blockIdx.y * 16384;
    int i = blockIdx.x * 256 + threadIdx.x;
    int n = i >> 7, k = i & 127;
    dst[n * 128 + k] = __float2bfloat16(W[k * 128 + n]);
}

// prep: split edge meta (idx / bf16 add) + CSR starts
__global__ void __launch_bounds__(256)
prep_edge(const int* __restrict__ segs, const int* __restrict__ nidx,
          const float4* __restrict__ add, int* __restrict__ eidx,
          uint2* __restrict__ eadd, int* __restrict__ start, int E, int N)
{
    int i = blockIdx.x * 256 + threadIdx.x;
    if (i >= E) return;
    float4 ad = __ldg(add + i);
    __nv_bfloat162 lo = __floats2bfloat162_rn(ad.x, ad.y);
    __nv_bfloat162 hi = __floats2bfloat162_rn(ad.z, ad.w);
    eidx[i] = __ldg(nidx + i);
    eadd[i] = make_uint2(*reinterpret_cast<uint32_t*>(&lo),
                         *reinterpret_cast<uint32_t*>(&hi));
    int b = __ldg(segs + i);
    int a = (i == 0) ? -1 : __ldg(segs + i - 1);
    for (int s = a + 1; s <= b; s++) start[s] = i;
    if (i == E - 1)
        for (int s = b + 1; s <= N; s++) start[s] = E;
}

// ---------------------------------------------------------------------------
// GEMM kernels
// ---------------------------------------------------------------------------
// pre: Pb = bf16(A@W + bias)   (A fp32)
__global__ void __launch_bounds__(256, 3)
gemm_pre(const float* __restrict__ A, const __nv_bfloat16* __restrict__ Wt,
         const float* __restrict__ bias, __nv_bfloat16* __restrict__ Pb, int M)
{
    extern __shared__ char smem[];
    uint32_t sA = smem_u32(smem), sB = sA + SMEM_A;
    int tid = threadIdx.x, lane = tid & 31, wid = tid >> 5;
    int wm = wid & 1, wn = wid >> 1, g = lane >> 2, tg = lane & 3;
    int tile0 = blockIdx.x * 64;

    fill_A(smem, A, tile0, M, tid);
    fill_B(smem + SMEM_A, Wt, tid);
    __syncthreads();

    float acc[2][4][4];
#pragma unroll
    for (int mt = 0; mt < 2; mt++)
#pragma unroll
        for (int nt = 0; nt < 4; nt++)
#pragma unroll
            for (int j = 0; j < 4; j++) acc[mt][nt][j] = 0.f;
    mma_tile(sA, sB, acc, lane, wm, wn);

#pragma unroll
    for (int mt = 0; mt < 2; mt++) {
        int r0 = tile0 + wm * 32 + mt * 16 + g;
#pragma unroll
        for (int nt = 0; nt < 4; nt++) {
            int c0 = wn * 32 + nt * 8 + tg * 2;
            float b0 = __ldg(bias + c0), b1 = __ldg(bias + c0 + 1);
            if (r0 < M) {
                __nv_bfloat162 o = __floats2bfloat162_rn(acc[mt][nt][0] + b0,
                                                         acc[mt][nt][1] + b1);
                *reinterpret_cast<uint32_t*>(Pb + (size_t)r0 * 128 + c0) =
                    *reinterpret_cast<uint32_t*>(&o);
            }
            if (r0 + 8 < M) {
                __nv_bfloat162 o = __floats2bfloat162_rn(acc[mt][nt][2] + b0,
                                                         acc[mt][nt][3] + b1);
                *reinterpret_cast<uint32_t*>(Pb + (size_t)(r0 + 8) * 128 + c0) =
                    *reinterpret_cast<uint32_t*>(&o);
            }
        }
    }
}

// mid: x1 = interp + poolb@W1 + bo0 (fp32 out); then Pb = bf16(x1@W2 + bb1)
__global__ void __launch_bounds__(256, 2)
gemm_mid(const __nv_bfloat16* __restrict__ poolb,
         const __nv_bfloat16* __restrict__ Wt1,
         const float* __restrict__ bo0, const float* __restrict__ interp,
         float* __restrict__ x1, const __nv_bfloat16* __restrict__ Wt2,
         const float* __restrict__ bb1, __nv_bfloat16* __restrict__ Pb, int M)
{
    extern __shared__ char smem[];
    uint32_t sA = smem_u32(smem), sB1 = sA + SMEM_A, sB2 = sB1 + SMEM_B;
    int tid = threadIdx.x, lane = tid & 31, wid = tid >> 5;
    int wm = wid & 1, wn = wid >> 1, g = lane >> 2, tg = lane & 3;
    int tile0 = blockIdx.x * 64;

    fill_Abf(smem, poolb, tile0, M, tid);
    fill_B(smem + SMEM_A, Wt1, tid);
    fill_B(smem + SMEM_A + SMEM_B, Wt2, tid);
    __syncthreads();

    float acc[2][4][4];
#pragma unroll
    for (int mt = 0; mt < 2; mt++)
#pragma unroll
        for (int nt = 0; nt < 4; nt++)
#pragma unroll
            for (int j = 0; j < 4; j++) acc[mt][nt][j] = 0.f;
    mma_tile(sA, sB1, acc, lane, wm, wn);
    __syncthreads();                        // all reads of A done before overwrite

    // Phase-A epilogue: x1 = resid + acc + bias; fp32 -> gmem, bf16 -> A smem
#pragma unroll
    for (int mt = 0; mt < 2; mt++) {
        int rl = wm * 32 + mt * 16 + g;
        int r0 = tile0 + rl;
#pragma unroll
        for (int nt = 0; nt < 4; nt++) {
            int c0 = wn * 32 + nt * 8 + tg * 2;
            float b0 = __ldg(bo0 + c0), b1 = __ldg(bo0 + c0 + 1);
            if (r0 < M) {
                float2 rv = *reinterpret_cast<const float2*>(
                    interp + (size_t)r0 * 128 + c0);
                float v0 = acc[mt][nt][0] + b0 + rv.x;
                float v1 = acc[mt][nt][1] + b1 + rv.y;
                *reinterpret_cast<float2*>(x1 + (size_t)r0 * 128 + c0) =
                    make_float2(v0, v1);
                __nv_bfloat162 o = __floats2bfloat162_rn(v0, v1);
                *reinterpret_cast<uint32_t*>(smem + rl * (BSTR * 2) + c0 * 2) =
                    *reinterpret_cast<uint32_t*>(&o);
            }
            if (r0 + 8 < M) {
                float2 rv = *reinterpret_cast<const float2*>(
                    interp + (size_t)(r0 + 8) * 128 + c0);
                float v0 = acc[mt][nt][2] + b0 + rv.x;
                float v1 = acc[mt][nt][3] + b1 + rv.y;
                *reinterpret_cast<float2*>(x1 + (size_t)(r0 + 8) * 128 + c0) =
                    make_float2(v0, v1);
                __nv_bfloat162 o = __floats2bfloat162_rn(v0, v1);
                *reinterpret_cast<uint32_t*>(smem + (rl + 8) * (BSTR * 2) + c0 * 2) =
                    *reinterpret_cast<uint32_t*>(&o);
            }
        }
    }
    __syncthreads();

    // Phase B: Pb = bf16(x1@W2 + bb1)
#pragma unroll
    for (int mt = 0; mt < 2; mt++)
#pragma unroll
        for (int nt = 0; nt < 4; nt++)
#pragma unroll
            for (int j = 0; j < 4; j++) acc[mt][nt][j] = 0.f;
    mma_tile(sA, sB2, acc, lane, wm, wn);

#pragma unroll
    for (int mt = 0; mt < 2; mt++) {
        int r0 = tile0 + wm * 32 + mt * 16 + g;
#pragma unroll
        for (int nt = 0; nt < 4; nt++) {
            int c0 = wn * 32 + nt * 8 + tg * 2;
            float b0 = __ldg(bb1 + c0), b1 = __ldg(bb1 + c0 + 1);
            if (r0 < M) {
                __nv_bfloat162 o = __floats2bfloat162_rn(acc[mt][nt][0] + b0,
                                                         acc[mt][nt][1] + b1);
                *reinterpret_cast<uint32_t*>(Pb + (size_t)r0 * 128 + c0) =
                    *reinterpret_cast<uint32_t*>(&o);
            }
            if (r0 + 8 < M) {
                __nv_bfloat162 o = __floats2bfloat162_rn(acc[mt][nt][2] + b0,
                                                         acc[mt][nt][3] + b1);
                *reinterpret_cast<uint32_t*>(Pb + (size_t)(r0 + 8) * 128 + c0) =
                    *reinterpret_cast<uint32_t*>(&o);
            }
        }
    }
}

// fin: out = (x1 + poolb@W3 + bo1) @ Wf + bf
__global__ void __launch_bounds__(256, 3)
gemm_fin(const __nv_bfloat16* __restrict__ poolb,
         const __nv_bfloat16* __restrict__ Wt3,
         const float* __restrict__ bo1, const float* __restrict__ x1,
         const float* __restrict__ Wf, const float* __restrict__ bfp,
         float* __restrict__ out, int M)
{
    extern __shared__ char smem[];
    uint32_t sA = smem_u32(smem), sB = sA + SMEM_A;
    int tid = threadIdx.x, lane = tid & 31, wid = tid >> 5;
    int wm = wid & 1, wn = wid >> 1, g = lane >> 2, tg = lane & 3;
    int tile0 = blockIdx.x * 64;

    fill_Abf(smem, poolb, tile0, M, tid);
    fill_B(smem + SMEM_A, Wt3, tid);
    __syncthreads();

    float acc[2][4][4];
#pragma unroll
    for (int mt = 0; mt < 2; mt++)
#pragma unroll
        for (int nt = 0; nt < 4; nt++)
#pragma unroll
            for (int j = 0; j < 4; j++) acc[mt][nt][j] = 0.f;
    mma_tile(sA, sB, acc, lane, wm, wn);
    __syncthreads();                        // done with A/B smem -> reuse for hp

    float* hp = reinterpret_cast<float*>(smem);   // [64][17]
#pragma unroll
    for (int mt = 0; mt < 2; mt++) {
        int rl = wm * 32 + mt * 16 + g;
        int r0 = tile0 + rl;
        float plo = 0.f, phi = 0.f;
#pragma unroll
        for (int nt = 0; nt < 4; nt++) {
            int c0 = wn * 32 + nt * 8 + tg * 2;
            float b0 = __ldg(bo1 + c0), b1 = __ldg(bo1 + c0 + 1);
            float w0 = __ldg(Wf + c0),  w1 = __ldg(Wf + c0 + 1);
            float v0 = acc[mt][nt][0] + b0, v1 = acc[mt][nt][1] + b1;
            float u0 = acc[mt][nt][2] + b0, u1 = acc[mt][nt][3] + b1;
            if (r0 < M) {
                float2 rv = *reinterpret_cast<const float2*>(
                    x1 + (size_t)r0 * 128 + c0);
                plo += (v0 + rv.x) * w0 + (v1 + rv.y) * w1;
            }
            if (r0 + 8 < M) {
                float2 rv = *reinterpret_cast<const float2*>(
                    x1 + (size_t)(r0 + 8) * 128 + c0);
                phi += (u0 + rv.x) * w0 + (u1 + rv.y) * w1;
            }
        }
        hp[rl * 17 + wn * 4 + tg] = plo;
        hp[(rl + 8) * 17 + wn * 4 + tg] = phi;
    }
    __syncthreads();
    if (tid < 64) {
        int r0 = tile0 + tid;
        if (r0 < M) {
            float s = 0.f;
#pragma unroll
            for (int j = 0; j < 16; j++) s += hp[tid * 17 + j];
            out[r0] = s + __ldg(bfp);
        }
    }
}

// ---------------------------------------------------------------------------
// Edge kernel (CSR, full warp per edge, decoupled prefetch): warp owns one
// segment. idx prefetched 3 iterations ahead (breaks the meta->P serial
// chain), P rows + add-info prefetched 2 ahead. Clamped-tail addressing
// (re-reads last edge; compute runs exactly len times). h = P[idx] +
// add@Wadd (HFMA2); running max (HMAX2, zero-init = relu fold); plain uint2
// store. No atomics, no zeroing. Thread owns 4 columns.
// ---------------------------------------------------------------------------
#define EDGE_PROC(ad, pv) do {                                               \
    __nv_bfloat162 axy = *reinterpret_cast<__nv_bfloat162*>(&(ad).x);        \
    __nv_bfloat162 azw = *reinterpret_cast<__nv_bfloat162*>(&(ad).y);        \
    __nv_bfloat162 ax = __low2bfloat162(axy),  ay = __high2bfloat162(axy);   \
    __nv_bfloat162 az = __low2bfloat162(azw),  aw = __high2bfloat162(azw);   \
    __nv_bfloat162 h0 = *reinterpret_cast<__nv_bfloat162*>(&(pv).x);         \
    __nv_bfloat162 h1 = *reinterpret_cast<__nv_bfloat162*>(&(pv).y);         \
    h0 = __hfma2(ax, wa2[0][0], h0); h1 = __hfma2(ax, wa2[0][1], h1);        \
    h0 = __hfma2(ay, wa2[1][0], h0); h1 = __hfma2(ay, wa2[1][1], h1);        \
    h0 = __hfma2(az, wa2[2][0], h0); h1 = __hfma2(az, wa2[2][1], h1);        \
    h0 = __hfma2(aw, wa2[3][0], h0); h1 = __hfma2(aw, wa2[3][1], h1);        \
    m0 = __hmax2(m0, h0); m1 = __hmax2(m1, h1);                              \
} while (0)

__global__ void __launch_bounds__(256)
edge_kernel(const uint2* __restrict__ Pr, const int* __restrict__ eidx,
            const uint2* __restrict__ eadd, const int* __restrict__ start,
            const float* __restrict__ Wadd, uint2* __restrict__ poolb, int N)
{
    int s = blockIdx.x * 8 + (threadIdx.x >> 5);
    if (s >= N) return;
    int lane = threadIdx.x & 31;
    int e0 = __ldg(start + s), en = __ldg(start + s + 1);

    int cb = lane * 4;
    __nv_bfloat162 wa2[4][2];
#pragma unroll
    for (int a = 0; a < 4; a++)
#pragma unroll
        for (int p = 0; p < 2; p++)
            wa2[a][p] = __floats2bfloat162_rn(__ldg(Wadd + a * 128 + cb + 2 * p),
                                              __ldg(Wadd + a * 128 + cb + 2 * p + 1));

    __nv_bfloat162 z2 = __floats2bfloat162_rn(0.f, 0.f);
    __nv_bfloat162 m0 = z2, m1 = z2;

    int len = en - e0;
    if (len > 0) {
        int last = en - 1;
#define EPOS(t) (e0 + (t) < last ? e0 + (t) : last)
        int   i0  = __ldg(eidx + EPOS(0));
        int   i1  = __ldg(eidx + EPOS(1));
        int   i2  = __ldg(eidx + EPOS(2));
        uint2 pv0 = __ldg(Pr + (size_t)i0 * 32 + lane);
        uint2 pv1 = __ldg(Pr + (size_t)i1 * 32 + lane);
        uint2 ad0 = __ldg(eadd + EPOS(0));
        uint2 ad1 = __ldg(eadd + EPOS(1));
#pragma unroll 2
        for (int t = 0; t < len; t++) {
            uint2 pv2 = __ldg(Pr + (size_t)i2 * 32 + lane);
            uint2 ad2 = __ldg(eadd + EPOS(t + 2));
            int   i3  = __ldg(eidx + EPOS(t + 3));
            EDGE_PROC(ad0, pv0);
            i2 = i3;
            pv0 = pv1; pv1 = pv2;
            ad0 = ad1; ad1 = ad2;
        }
#undef EPOS
    }

    uint2 o;
    o.x = *reinterpret_cast<uint32_t*>(&m0);
    o.y = *reinterpret_cast<uint32_t*>(&m1);
    poolb[(size_t)s * 32 + lane] = o;
}

// ---------------------------------------------------------------------------
extern "C" void kernel_launch(void* const* d_in, const int* in_sizes, int n_in,
                              void* d_out, int out_size)
{
    const float* interp = (const float*)d_in[0];
    const float* add    = (const float*)d_in[1];
    const int*   nidx   = (const int*)d_in[2];
    const int*   segs   = (const int*)d_in[3];
    const float* Wb0 = (const float*)d_in[4];
    const float* bb0 = (const float*)d_in[5];
    const float* Wo0 = (const float*)d_in[6];
    const float* bo0 = (const float*)d_in[7];
    const float* Wb1 = (const float*)d_in[8];
    const float* bb1 = (const float*)d_in[9];
    const float* Wo1 = (const float*)d_in[10];
    const float* bo1 = (const float*)d_in[11];
    const float* Wf  = (const float*)d_in[12];
    const float* bf  = (const float*)d_in[13];
    float* out = (float*)d_out;

    int N = in_sizes[0] / 128;
    int E = in_sizes[2];

    __nv_bfloat16 *P, *poolb, *Wt;
    float *x1;
    int *eidx, *start;
    uint2* eadd;
    cudaGetSymbolAddress((void**)&P, g_P);
    cudaGetSymbolAddress((void**)&poolb, g_poolb);
    cudaGetSymbolAddress((void**)&x1, g_x1);
    cudaGetSymbolAddress((void**)&Wt, g_Wt);
    cudaGetSymbolAddress((void**)&eidx, g_eidx);
    cudaGetSymbolAddress((void**)&eadd, g_eadd);
    cudaGetSymbolAddress((void**)&start, g_start);

    cudaFuncSetAttribute(gemm_pre, cudaFuncAttributeMaxDynamicSharedMemorySize, SMEM_PF);
    cudaFuncSetAttribute(gemm_mid, cudaFuncAttributeMaxDynamicSharedMemorySize, SMEM_MID);
    cudaFuncSetAttribute(gemm_fin, cudaFuncAttributeMaxDynamicSharedMemorySize, SMEM_PF);

    int gtiles = (N + 63) / 64;
    int sgrid = (N + 7) / 8;

    prep_w<<<dim3(64, 4), 256>>>(Wb0, Wo0, Wb1, Wo1, Wt);
    prep_edge<<<(E + 255) / 256, 256>>>(segs, nidx, (const float4*)add,
                                        eidx, eadd, start, E, N);

    // Block 0
    gemm_pre<<<gtiles, 256, SMEM_PF>>>(interp, Wt + 0 * 16384, bb0, P, N);
    edge_kernel<<<sgrid, 256>>>((const uint2*)P, eidx, eadd, start,
                                Wb0 + 128 * 128, (uint2*)poolb, N);
    // Block-0 projection + Block-1 pre-edge GEMM fused
    gemm_mid<<<gtiles, 256, SMEM_MID>>>(poolb, Wt + 1 * 16384, bo0, interp, x1,
                                        Wt + 2 * 16384, bb1, P, N);
    edge_kernel<<<sgrid, 256>>>((const uint2*)P, eidx, eadd, start,
                                Wb1 + 128 * 128, (uint2*)poolb, N);
    // Block-1 projection + final head fused
    gemm_fin<<<gtiles, 256, SMEM_PF>>>(poolb, Wt + 3 * 16384, bo1, x1, Wf, bf,
                                       out, N);
}

// round 11
// speedup vs baseline: 1.3294x; 1.3294x over previous
#include <cuda_runtime.h>
#include <cuda_bf16.h>
#include <cstdint>

// ---------------------------------------------------------------------------
// Problem shape (fixed by dataset): N=50000, E=1.6M, D=128, A=4, H=128
// ---------------------------------------------------------------------------
#define NMAX 50048          // 782 tiles of 64
#define EMAX 1700000
#define DDIM 128

__device__ __nv_bfloat16 g_P[(size_t)NMAX * DDIM];      // bf16 activations (pre-edge)
__device__ __nv_bfloat16 g_poolb[(size_t)NMAX * DDIM];  // bf16 pooled output
__device__ float g_x1  [(size_t)NMAX * DDIM];           // fp32 residual stream
__device__ __nv_bfloat16 g_Wt[4 * 128 * 128];           // transposed bf16 weights
__device__ uint4 g_edge[EMAX];                          // packed {idx, bf16 add x4, 0}
__device__ int   g_start[NMAX + 1];                     // CSR segment starts

// ---------------------------------------------------------------------------
// helpers
// ---------------------------------------------------------------------------
__device__ __forceinline__ uint32_t smem_u32(const void* p) {
    uint32_t a;
    asm("{ .reg .u64 t; cvta.to.shared.u64 t, %1; cvt.u32.u64 %0, t; }"
        : "=r"(a) : "l"(p));
    return a;
}
__device__ __forceinline__ void ldsm_x4(uint32_t& r0, uint32_t& r1,
                                        uint32_t& r2, uint32_t& r3, uint32_t a) {
    asm volatile("ldmatrix.sync.aligned.m8n8.x4.shared.b16 {%0,%1,%2,%3}, [%4];"
                 : "=r"(r0), "=r"(r1), "=r"(r2), "=r"(r3) : "r"(a));
}
__device__ __forceinline__ void ldsm_x2(uint32_t& r0, uint32_t& r1, uint32_t a) {
    asm volatile("ldmatrix.sync.aligned.m8n8.x2.shared.b16 {%0,%1}, [%2];"
                 : "=r"(r0), "=r"(r1) : "r"(a));
}
__device__ __forceinline__ void mma_bf16(float* c, const uint32_t* a, const uint32_t* b) {
    asm volatile(
        "mma.sync.aligned.m16n8k16.row.col.f32.bf16.bf16.f32 "
        "{%0,%1,%2,%3}, {%4,%5,%6,%7}, {%8,%9}, {%0,%1,%2,%3};"
        : "+f"(c[0]), "+f"(c[1]), "+f"(c[2]), "+f"(c[3])
        : "r"(a[0]), "r"(a[1]), "r"(a[2]), "r"(a[3]), "r"(b[0]), "r"(b[1]));
}

// ---------------------------------------------------------------------------
// Tiling constants: CTA = 64 rows x 128 cols, 8 warps (2 m x 4 n), K=128
// ---------------------------------------------------------------------------
#define BSTR 136                              // bf16 elems per smem row (pad 8)
static constexpr int SMEM_A  = 64 * BSTR * 2;    // 17408
static constexpr int SMEM_B  = 128 * BSTR * 2;   // 34816
static constexpr int SMEM_PF = SMEM_A + SMEM_B;          // 52224 (all gemms)

// A tile fill: 64x128 fp32 -> bf16 smem
__device__ __forceinline__ void fill_A(char* smem, const float* __restrict__ A,
                                       int tile0, int M, int tid) {
#pragma unroll
    for (int it = 0; it < 8; it++) {
        int p = it * 256 + tid;               // 0..2047
        int r = p >> 5, c = p & 31;
        int gr = tile0 + r;
        float4 v = make_float4(0.f, 0.f, 0.f, 0.f);
        if (gr < M) v = __ldg(reinterpret_cast<const float4*>(A + (size_t)gr * 128) + c);
        __nv_bfloat162 lo = __floats2bfloat162_rn(v.x, v.y);
        __nv_bfloat162 hi = __floats2bfloat162_rn(v.z, v.w);
        uint2 o = make_uint2(*reinterpret_cast<uint32_t*>(&lo),
                             *reinterpret_cast<uint32_t*>(&hi));
        *reinterpret_cast<uint2*>(smem + r * (BSTR * 2) + c * 8) = o;
    }
}
// A tile fill from bf16 source (straight copy)
__device__ __forceinline__ void fill_Abf(char* smem, const __nv_bfloat16* __restrict__ A,
                                         int tile0, int M, int tid) {
    const uint4* src = reinterpret_cast<const uint4*>(A + (size_t)tile0 * 128);
#pragma unroll
    for (int it = 0; it < 4; it++) {
        int p = it * 256 + tid;               // 0..1023
        int r = p >> 4, c = p & 15;
        uint4 v = make_uint4(0, 0, 0, 0);
        if (tile0 + r < M) v = __ldg(src + p);
        *reinterpret_cast<uint4*>(smem + r * (BSTR * 2) + c * 16) = v;
    }
}
// B tile fill: 128x128 bf16 (pre-transposed) -> smem, uint4 copies
__device__ __forceinline__ void fill_B(char* dst, const __nv_bfloat16* __restrict__ Wt,
                                       int tid) {
    const uint4* src = reinterpret_cast<const uint4*>(Wt);
#pragma unroll
    for (int it = 0; it < 8; it++) {
        int p = it * 256 + tid;               // 0..2047
        int n = p >> 4, c = p & 15;
        *reinterpret_cast<uint4*>(dst + n * (BSTR * 2) + c * 16) = src[p];
    }
}
// MMA core: acc[2][4][4] over 64x128 tile
__device__ __forceinline__ void mma_tile(uint32_t sA, uint32_t sB,
                                         float acc[2][4][4], int lane,
                                         int wm, int wn) {
    int aRow = wm * 32 + (lane & 15);
    int aCol = (lane >> 4) * 8;
    int bRow = wn * 32 + (lane & 7);
    int bCol = ((lane >> 3) & 1) * 8;
#pragma unroll
    for (int k = 0; k < 8; k++) {
        uint32_t a[2][4], b[4][2];
#pragma unroll
        for (int mt = 0; mt < 2; mt++)
            ldsm_x4(a[mt][0], a[mt][1], a[mt][2], a[mt][3],
                    sA + (aRow + mt * 16) * (BSTR * 2) + (k * 16 + aCol) * 2);
#pragma unroll
        for (int nt = 0; nt < 4; nt++)
            ldsm_x2(b[nt][0], b[nt][1],
                    sB + (bRow + nt * 8) * (BSTR * 2) + (k * 16 + bCol) * 2);
#pragma unroll
        for (int mt = 0; mt < 2; mt++)
#pragma unroll
            for (int nt = 0; nt < 4; nt++)
                mma_bf16(acc[mt][nt], a[mt], b[nt]);
    }
}

// ---------------------------------------------------------------------------
// prep: Wt[w][n][k] = bf16(W_w[k][n])
// ---------------------------------------------------------------------------
__global__ void __launch_bounds__(256)
prep_w(const float* __restrict__ W0, const float* __restrict__ W1,
       const float* __restrict__ W2, const float* __restrict__ W3,
       __nv_bfloat16* __restrict__ Wt)
{
    const float* Ws[4] = {W0, W1, W2, W3};
    const float* W = Ws[blockIdx.y];
    __nv_bfloat16* dst = Wt + (size_t)blockIdx.y * 16384;
    int i = blockIdx.x * 256 + threadIdx.x;
    int n = i >> 7, k = i & 127;
    dst[n * 128 + k] = __float2bfloat16(W[k * 128 + n]);
}

// prep: pack per-edge meta {idx, bf16(add.xy), bf16(add.zw), 0} + CSR starts
__global__ void __launch_bounds__(256)
prep_edge(const int* __restrict__ segs, const int* __restrict__ nidx,
          const float4* __restrict__ add, uint4* __restrict__ em,
          int* __restrict__ start, int E, int N)
{
    int i = blockIdx.x * 256 + threadIdx.x;
    if (i >= E) return;
    float4 ad = __ldg(add + i);
    __nv_bfloat162 lo = __floats2bfloat162_rn(ad.x, ad.y);
    __nv_bfloat162 hi = __floats2bfloat162_rn(ad.z, ad.w);
    em[i] = make_uint4((uint32_t)__ldg(nidx + i),
                       *reinterpret_cast<uint32_t*>(&lo),
                       *reinterpret_cast<uint32_t*>(&hi), 0u);
    int b = __ldg(segs + i);
    int a = (i == 0) ? -1 : __ldg(segs + i - 1);
    for (int s = a + 1; s <= b; s++) start[s] = i;
    if (i == E - 1)
        for (int s = b + 1; s <= N; s++) start[s] = E;
}

// ---------------------------------------------------------------------------
// GEMM kernels
// ---------------------------------------------------------------------------
// pre: Pb = bf16(A@W + bias)   (A fp32)
__global__ void __launch_bounds__(256, 3)
gemm_pre(const float* __restrict__ A, const __nv_bfloat16* __restrict__ Wt,
         const float* __restrict__ bias, __nv_bfloat16* __restrict__ Pb, int M)
{
    extern __shared__ char smem[];
    uint32_t sA = smem_u32(smem), sB = sA + SMEM_A;
    int tid = threadIdx.x, lane = tid & 31, wid = tid >> 5;
    int wm = wid & 1, wn = wid >> 1, g = lane >> 2, tg = lane & 3;
    int tile0 = blockIdx.x * 64;

    fill_A(smem, A, tile0, M, tid);
    fill_B(smem + SMEM_A, Wt, tid);
    __syncthreads();

    float acc[2][4][4];
#pragma unroll
    for (int mt = 0; mt < 2; mt++)
#pragma unroll
        for (int nt = 0; nt < 4; nt++)
#pragma unroll
            for (int j = 0; j < 4; j++) acc[mt][nt][j] = 0.f;
    mma_tile(sA, sB, acc, lane, wm, wn);

#pragma unroll
    for (int mt = 0; mt < 2; mt++) {
        int r0 = tile0 + wm * 32 + mt * 16 + g;
#pragma unroll
        for (int nt = 0; nt < 4; nt++) {
            int c0 = wn * 32 + nt * 8 + tg * 2;
            float b0 = __ldg(bias + c0), b1 = __ldg(bias + c0 + 1);
            if (r0 < M) {
                __nv_bfloat162 o = __floats2bfloat162_rn(acc[mt][nt][0] + b0,
                                                         acc[mt][nt][1] + b1);
                *reinterpret_cast<uint32_t*>(Pb + (size_t)r0 * 128 + c0) =
                    *reinterpret_cast<uint32_t*>(&o);
            }
            if (r0 + 8 < M) {
                __nv_bfloat162 o = __floats2bfloat162_rn(acc[mt][nt][2] + b0,
                                                         acc[mt][nt][3] + b1);
                *reinterpret_cast<uint32_t*>(Pb + (size_t)(r0 + 8) * 128 + c0) =
                    *reinterpret_cast<uint32_t*>(&o);
            }
        }
    }
}

// mid: x1 = interp + poolb@W1 + bo0 (fp32 out); then Pb = bf16(x1@W2 + bb1)
// Single B buffer: refill with Wt2 during phase-A epilogue -> 3 CTAs/SM.
__global__ void __launch_bounds__(256, 3)
gemm_mid(const __nv_bfloat16* __restrict__ poolb,
         const __nv_bfloat16* __restrict__ Wt1,
         const float* __restrict__ bo0, const float* __restrict__ interp,
         float* __restrict__ x1, const __nv_bfloat16* __restrict__ Wt2,
         const float* __restrict__ bb1, __nv_bfloat16* __restrict__ Pb, int M)
{
    extern __shared__ char smem[];
    uint32_t sA = smem_u32(smem), sB = sA + SMEM_A;
    int tid = threadIdx.x, lane = tid & 31, wid = tid >> 5;
    int wm = wid & 1, wn = wid >> 1, g = lane >> 2, tg = lane & 3;
    int tile0 = blockIdx.x * 64;

    fill_Abf(smem, poolb, tile0, M, tid);
    fill_B(smem + SMEM_A, Wt1, tid);
    __syncthreads();

    float acc[2][4][4];
#pragma unroll
    for (int mt = 0; mt < 2; mt++)
#pragma unroll
        for (int nt = 0; nt < 4; nt++)
#pragma unroll
            for (int j = 0; j < 4; j++) acc[mt][nt][j] = 0.f;
    mma_tile(sA, sB, acc, lane, wm, wn);
    __syncthreads();                        // all reads of A and B done

    // Phase-A epilogue: x1 = resid + acc + bias; fp32 -> gmem, bf16 -> A smem.
    // Meanwhile refill B smem with Wt2.
    fill_B(smem + SMEM_A, Wt2, tid);
#pragma unroll
    for (int mt = 0; mt < 2; mt++) {
        int rl = wm * 32 + mt * 16 + g;
        int r0 = tile0 + rl;
#pragma unroll
        for (int nt = 0; nt < 4; nt++) {
            int c0 = wn * 32 + nt * 8 + tg * 2;
            float b0 = __ldg(bo0 + c0), b1 = __ldg(bo0 + c0 + 1);
            if (r0 < M) {
                float2 rv = *reinterpret_cast<const float2*>(
                    interp + (size_t)r0 * 128 + c0);
                float v0 = acc[mt][nt][0] + b0 + rv.x;
                float v1 = acc[mt][nt][1] + b1 + rv.y;
                *reinterpret_cast<float2*>(x1 + (size_t)r0 * 128 + c0) =
                    make_float2(v0, v1);
                __nv_bfloat162 o = __floats2bfloat162_rn(v0, v1);
                *reinterpret_cast<uint32_t*>(smem + rl * (BSTR * 2) + c0 * 2) =
                    *reinterpret_cast<uint32_t*>(&o);
            }
            if (r0 + 8 < M) {
                float2 rv = *reinterpret_cast<const float2*>(
                    interp + (size_t)(r0 + 8) * 128 + c0);
                float v0 = acc[mt][nt][2] + b0 + rv.x;
                float v1 = acc[mt][nt][3] + b1 + rv.y;
                *reinterpret_cast<float2*>(x1 + (size_t)(r0 + 8) * 128 + c0) =
                    make_float2(v0, v1);
                __nv_bfloat162 o = __floats2bfloat162_rn(v0, v1);
                *reinterpret_cast<uint32_t*>(smem + (rl + 8) * (BSTR * 2) + c0 * 2) =
                    *reinterpret_cast<uint32_t*>(&o);
            }
        }
    }
    __syncthreads();

    // Phase B: Pb = bf16(x1@W2 + bb1)
#pragma unroll
    for (int mt = 0; mt < 2; mt++)
#pragma unroll
        for (int nt = 0; nt < 4; nt++)
#pragma unroll
            for (int j = 0; j < 4; j++) acc[mt][nt][j] = 0.f;
    mma_tile(sA, sB, acc, lane, wm, wn);

#pragma unroll
    for (int mt = 0; mt < 2; mt++) {
        int r0 = tile0 + wm * 32 + mt * 16 + g;
#pragma unroll
        for (int nt = 0; nt < 4; nt++) {
            int c0 = wn * 32 + nt * 8 + tg * 2;
            float b0 = __ldg(bb1 + c0), b1 = __ldg(bb1 + c0 + 1);
            if (r0 < M) {
                __nv_bfloat162 o = __floats2bfloat162_rn(acc[mt][nt][0] + b0,
                                                         acc[mt][nt][1] + b1);
                *reinterpret_cast<uint32_t*>(Pb + (size_t)r0 * 128 + c0) =
                    *reinterpret_cast<uint32_t*>(&o);
            }
            if (r0 + 8 < M) {
                __nv_bfloat162 o = __floats2bfloat162_rn(acc[mt][nt][2] + b0,
                                                         acc[mt][nt][3] + b1);
                *reinterpret_cast<uint32_t*>(Pb + (size_t)(r0 + 8) * 128 + c0) =
                    *reinterpret_cast<uint32_t*>(&o);
            }
        }
    }
}

// fin: out = (x1 + poolb@W3 + bo1) @ Wf + bf
__global__ void __launch_bounds__(256, 3)
gemm_fin(const __nv_bfloat16* __restrict__ poolb,
         const __nv_bfloat16* __restrict__ Wt3,
         const float* __restrict__ bo1, const float* __restrict__ x1,
         const float* __restrict__ Wf, const float* __restrict__ bfp,
         float* __restrict__ out, int M)
{
    extern __shared__ char smem[];
    uint32_t sA = smem_u32(smem), sB = sA + SMEM_A;
    int tid = threadIdx.x, lane = tid & 31, wid = tid >> 5;
    int wm = wid & 1, wn = wid >> 1, g = lane >> 2, tg = lane & 3;
    int tile0 = blockIdx.x * 64;

    fill_Abf(smem, poolb, tile0, M, tid);
    fill_B(smem + SMEM_A, Wt3, tid);
    __syncthreads();

    float acc[2][4][4];
#pragma unroll
    for (int mt = 0; mt < 2; mt++)
#pragma unroll
        for (int nt = 0; nt < 4; nt++)
#pragma unroll
            for (int j = 0; j < 4; j++) acc[mt][nt][j] = 0.f;
    mma_tile(sA, sB, acc, lane, wm, wn);
    __syncthreads();                        // done with A/B smem -> reuse for hp

    float* hp = reinterpret_cast<float*>(smem);   // [64][17]
#pragma unroll
    for (int mt = 0; mt < 2; mt++) {
        int rl = wm * 32 + mt * 16 + g;
        int r0 = tile0 + rl;
        float plo = 0.f, phi = 0.f;
#pragma unroll
        for (int nt = 0; nt < 4; nt++) {
            int c0 = wn * 32 + nt * 8 + tg * 2;
            float b0 = __ldg(bo1 + c0), b1 = __ldg(bo1 + c0 + 1);
            float w0 = __ldg(Wf + c0),  w1 = __ldg(Wf + c0 + 1);
            float v0 = acc[mt][nt][0] + b0, v1 = acc[mt][nt][1] + b1;
            float u0 = acc[mt][nt][2] + b0, u1 = acc[mt][nt][3] + b1;
            if (r0 < M) {
                float2 rv = *reinterpret_cast<const float2*>(
                    x1 + (size_t)r0 * 128 + c0);
                plo += (v0 + rv.x) * w0 + (v1 + rv.y) * w1;
            }
            if (r0 + 8 < M) {
                float2 rv = *reinterpret_cast<const float2*>(
                    x1 + (size_t)(r0 + 8) * 128 + c0);
                phi += (u0 + rv.x) * w0 + (u1 + rv.y) * w1;
            }
        }
        hp[rl * 17 + wn * 4 + tg] = plo;
        hp[(rl + 8) * 17 + wn * 4 + tg] = phi;
    }
    __syncthreads();
    if (tid < 64) {
        int r0 = tile0 + tid;
        if (r0 < M) {
            float s = 0.f;
#pragma unroll
            for (int j = 0; j < 16; j++) s += hp[tid * 17 + j];
            out[r0] = s + __ldg(bfp);
        }
    }
}

// ---------------------------------------------------------------------------
// Edge kernel (CSR, full warp per edge, manual 2-wide): warp owns one
// segment; per iteration load two metas, then both P rows (MLP=2 on the
// meta->P chains), process both. h = P[idx] + add@Wadd (HFMA2); running max
// (HMAX2, zero-init = relu fold); plain uint2 store. No atomics, no zeroing.
// Thread owns 4 columns. launch_bounds(256,5): regs<=51, no spills.
// ---------------------------------------------------------------------------
#define EDGE_PROC(md, pv) do {                                               \
    __nv_bfloat162 axy = *reinterpret_cast<__nv_bfloat162*>(&(md).y);        \
    __nv_bfloat162 azw = *reinterpret_cast<__nv_bfloat162*>(&(md).z);        \
    __nv_bfloat162 ax = __low2bfloat162(axy),  ay = __high2bfloat162(axy);   \
    __nv_bfloat162 az = __low2bfloat162(azw),  aw = __high2bfloat162(azw);   \
    __nv_bfloat162 h0 = *reinterpret_cast<__nv_bfloat162*>(&(pv).x);         \
    __nv_bfloat162 h1 = *reinterpret_cast<__nv_bfloat162*>(&(pv).y);         \
    h0 = __hfma2(ax, wa2[0][0], h0); h1 = __hfma2(ax, wa2[0][1], h1);        \
    h0 = __hfma2(ay, wa2[1][0], h0); h1 = __hfma2(ay, wa2[1][1], h1);        \
    h0 = __hfma2(az, wa2[2][0], h0); h1 = __hfma2(az, wa2[2][1], h1);        \
    h0 = __hfma2(aw, wa2[3][0], h0); h1 = __hfma2(aw, wa2[3][1], h1);        \
    m0 = __hmax2(m0, h0); m1 = __hmax2(m1, h1);                              \
} while (0)

__global__ void __launch_bounds__(256, 5)
edge_kernel(const uint2* __restrict__ Pr, const uint4* __restrict__ em,
            const int* __restrict__ start, const float* __restrict__ Wadd,
            uint2* __restrict__ poolb, int N)
{
    int s = blockIdx.x * 8 + (threadIdx.x >> 5);
    if (s >= N) return;
    int lane = threadIdx.x & 31;
    int e  = __ldg(start + s);
    int en = __ldg(start + s + 1);

    int cb = lane * 4;
    __nv_bfloat162 wa2[4][2];
#pragma unroll
    for (int a = 0; a < 4; a++)
#pragma unroll
        for (int p = 0; p < 2; p++)
            wa2[a][p] = __floats2bfloat162_rn(__ldg(Wadd + a * 128 + cb + 2 * p),
                                              __ldg(Wadd + a * 128 + cb + 2 * p + 1));

    __nv_bfloat162 z2 = __floats2bfloat162_rn(0.f, 0.f);
    __nv_bfloat162 m0 = z2, m1 = z2;

    for (; e + 2 <= en; e += 2) {
        uint4 mdA = __ldg(em + e);
        uint4 mdB = __ldg(em + e + 1);
        uint2 pvA = __ldg(Pr + (size_t)mdA.x * 32 + lane);
        uint2 pvB = __ldg(Pr + (size_t)mdB.x * 32 + lane);
        EDGE_PROC(mdA, pvA);
        EDGE_PROC(mdB, pvB);
    }
    if (e < en) {
        uint4 md = __ldg(em + e);
        uint2 pv = __ldg(Pr + (size_t)md.x * 32 + lane);
        EDGE_PROC(md, pv);
    }

    uint2 o;
    o.x = *reinterpret_cast<uint32_t*>(&m0);
    o.y = *reinterpret_cast<uint32_t*>(&m1);
    poolb[(size_t)s * 32 + lane] = o;
}

// ---------------------------------------------------------------------------
extern "C" void kernel_launch(void* const* d_in, const int* in_sizes, int n_in,
                              void* d_out, int out_size)
{
    const float* interp = (const float*)d_in[0];
    const float* add    = (const float*)d_in[1];
    const int*   nidx   = (const int*)d_in[2];
    const int*   segs   = (const int*)d_in[3];
    const float* Wb0 = (const float*)d_in[4];
    const float* bb0 = (const float*)d_in[5];
    const float* Wo0 = (const float*)d_in[6];
    const float* bo0 = (const float*)d_in[7];
    const float* Wb1 = (const float*)d_in[8];
    const float* bb1 = (const float*)d_in[9];
    const float* Wo1 = (const float*)d_in[10];
    const float* bo1 = (const float*)d_in[11];
    const float* Wf  = (const float*)d_in[12];
    const float* bf  = (const float*)d_in[13];
    float* out = (float*)d_out;

    int N = in_sizes[0] / 128;
    int E = in_sizes[2];

    __nv_bfloat16 *P, *poolb, *Wt;
    float *x1;
    uint4* em;
    int* start;
    cudaGetSymbolAddress((void**)&P, g_P);
    cudaGetSymbolAddress((void**)&poolb, g_poolb);
    cudaGetSymbolAddress((void**)&x1, g_x1);
    cudaGetSymbolAddress((void**)&Wt, g_Wt);
    cudaGetSymbolAddress((void**)&em, g_edge);
    cudaGetSymbolAddress((void**)&start, g_start);

    cudaFuncSetAttribute(gemm_pre, cudaFuncAttributeMaxDynamicSharedMemorySize, SMEM_PF);
    cudaFuncSetAttribute(gemm_mid, cudaFuncAttributeMaxDynamicSharedMemorySize, SMEM_PF);
    cudaFuncSetAttribute(gemm_fin, cudaFuncAttributeMaxDynamicSharedMemorySize, SMEM_PF);

    int gtiles = (N + 63) / 64;
    int sgrid = (N + 7) / 8;

    prep_w<<<dim3(64, 4), 256>>>(Wb0, Wo0, Wb1, Wo1, Wt);
    prep_edge<<<(E + 255) / 256, 256>>>(segs, nidx, (const float4*)add, em,
                                        start, E, N);

    // Block 0
    gemm_pre<<<gtiles, 256, SMEM_PF>>>(interp, Wt + 0 * 16384, bb0, P, N);
    edge_kernel<<<sgrid, 256>>>((const uint2*)P, em, start, Wb0 + 128 * 128,
                                (uint2*)poolb, N);
    // Block-0 projection + Block-1 pre-edge GEMM fused
    gemm_mid<<<gtiles, 256, SMEM_PF>>>(poolb, Wt + 1 * 16384, bo0, interp, x1,
                                       Wt + 2 * 16384, bb1, P, N);
    edge_kernel<<<sgrid, 256>>>((const uint2*)P, em, start, Wb1 + 128 * 128,
                                (uint2*)poolb, N);
    // Block-1 projection + final head fused
    gemm_fin<<<gtiles, 256, SMEM_PF>>>(poolb, Wt + 3 * 16384, bo1, x1, Wf, bf,
                                       out, N);
}

// round 12
// speedup vs baseline: 1.3849x; 1.0417x over previous
#include <cuda_runtime.h>
#include <cuda_bf16.h>
#include <cstdint>

// ---------------------------------------------------------------------------
// Problem shape (fixed by dataset): N=50000, E=1.6M, D=128, A=4, H=128
// ---------------------------------------------------------------------------
#define NMAX 50048          // 782 tiles of 64
#define EMAX 1700000
#define DDIM 128

__device__ __nv_bfloat16 g_P[(size_t)NMAX * DDIM];      // bf16 activations (pre-edge)
__device__ __nv_bfloat16 g_poolb[(size_t)NMAX * DDIM];  // bf16 pooled output
__device__ float g_x1  [(size_t)NMAX * DDIM];           // fp32 residual stream
__device__ __nv_bfloat16 g_Wt[4 * 128 * 128];           // transposed bf16 weights
__device__ int   g_eidx[EMAX];                          // edge neighbor index
__device__ uint2 g_eadd[EMAX];                          // edge add-info, bf16 x4
__device__ int   g_start[NMAX + 1];                     // CSR segment starts

// ---------------------------------------------------------------------------
// helpers
// ---------------------------------------------------------------------------
__device__ __forceinline__ uint32_t smem_u32(const void* p) {
    uint32_t a;
    asm("{ .reg .u64 t; cvta.to.shared.u64 t, %1; cvt.u32.u64 %0, t; }"
        : "=r"(a) : "l"(p));
    return a;
}
__device__ __forceinline__ void ldsm_x4(uint32_t& r0, uint32_t& r1,
                                        uint32_t& r2, uint32_t& r3, uint32_t a) {
    asm volatile("ldmatrix.sync.aligned.m8n8.x4.shared.b16 {%0,%1,%2,%3}, [%4];"
                 : "=r"(r0), "=r"(r1), "=r"(r2), "=r"(r3) : "r"(a));
}
__device__ __forceinline__ void ldsm_x2(uint32_t& r0, uint32_t& r1, uint32_t a) {
    asm volatile("ldmatrix.sync.aligned.m8n8.x2.shared.b16 {%0,%1}, [%2];"
                 : "=r"(r0), "=r"(r1) : "r"(a));
}
__device__ __forceinline__ void mma_bf16(float* c, const uint32_t* a, const uint32_t* b) {
    asm volatile(
        "mma.sync.aligned.m16n8k16.row.col.f32.bf16.bf16.f32 "
        "{%0,%1,%2,%3}, {%4,%5,%6,%7}, {%8,%9}, {%0,%1,%2,%3};"
        : "+f"(c[0]), "+f"(c[1]), "+f"(c[2]), "+f"(c[3])
        : "r"(a[0]), "r"(a[1]), "r"(a[2]), "r"(a[3]), "r"(b[0]), "r"(b[1]));
}
__device__ __forceinline__ void cpa8(uint32_t saddr, const void* gaddr) {
    asm volatile("cp.async.ca.shared.global [%0], [%1], 8;"
                 :: "r"(saddr), "l"(gaddr) : "memory");
}
#define CP_COMMIT() asm volatile("cp.async.commit_group;" ::: "memory")
#define CP_WAIT(n)  asm volatile("cp.async.wait_group %0;" :: "n"(n) : "memory")

// ---------------------------------------------------------------------------
// Tiling constants: CTA = 64 rows x 128 cols, 8 warps (2 m x 4 n), K=128
// ---------------------------------------------------------------------------
#define BSTR 136                              // bf16 elems per smem row (pad 8)
static constexpr int SMEM_A  = 64 * BSTR * 2;    // 17408
static constexpr int SMEM_B  = 128 * BSTR * 2;   // 34816
static constexpr int SMEM_PF = SMEM_A + SMEM_B;          // 52224 (pre/fin)
static constexpr int SMEM_MID = SMEM_A + 2 * SMEM_B;     // 87040 (mid)

// A tile fill: 64x128 fp32 -> bf16 smem
__device__ __forceinline__ void fill_A(char* smem, const float* __restrict__ A,
                                       int tile0, int M, int tid) {
#pragma unroll
    for (int it = 0; it < 8; it++) {
        int p = it * 256 + tid;               // 0..2047
        int r = p >> 5, c = p & 31;
        int gr = tile0 + r;
        float4 v = make_float4(0.f, 0.f, 0.f, 0.f);
        if (gr < M) v = __ldg(reinterpret_cast<const float4*>(A + (size_t)gr * 128) + c);
        __nv_bfloat162 lo = __floats2bfloat162_rn(v.x, v.y);
        __nv_bfloat162 hi = __floats2bfloat162_rn(v.z, v.w);
        uint2 o = make_uint2(*reinterpret_cast<uint32_t*>(&lo),
                             *reinterpret_cast<uint32_t*>(&hi));
        *reinterpret_cast<uint2*>(smem + r * (BSTR * 2) + c * 8) = o;
    }
}
// A tile fill from bf16 source (straight copy)
__device__ __forceinline__ void fill_Abf(char* smem, const __nv_bfloat16* __restrict__ A,
                                         int tile0, int M, int tid) {
    const uint4* src = reinterpret_cast<const uint4*>(A + (size_t)tile0 * 128);
#pragma unroll
    for (int it = 0; it < 4; it++) {
        int p = it * 256 + tid;               // 0..1023
        int r = p >> 4, c = p & 15;
        uint4 v = make_uint4(0, 0, 0, 0);
        if (tile0 + r < M) v = __ldg(src + p);
        *reinterpret_cast<uint4*>(smem + r * (BSTR * 2) + c * 16) = v;
    }
}
// B tile fill: 128x128 bf16 (pre-transposed) -> smem, uint4 copies
__device__ __forceinline__ void fill_B(char* dst, const __nv_bfloat16* __restrict__ Wt,
                                       int tid) {
    const uint4* src = reinterpret_cast<const uint4*>(Wt);
#pragma unroll
    for (int it = 0; it < 8; it++) {
        int p = it * 256 + tid;               // 0..2047
        int n = p >> 4, c = p & 15;
        *reinterpret_cast<uint4*>(dst + n * (BSTR * 2) + c * 16) = src[p];
    }
}
// MMA core: acc[2][4][4] over 64x128 tile
__device__ __forceinline__ void mma_tile(uint32_t sA, uint32_t sB,
                                         float acc[2][4][4], int lane,
                                         int wm, int wn) {
    int aRow = wm * 32 + (lane & 15);
    int aCol = (lane >> 4) * 8;
    int bRow = wn * 32 + (lane & 7);
    int bCol = ((lane >> 3) & 1) * 8;
#pragma unroll
    for (int k = 0; k < 8; k++) {
        uint32_t a[2][4], b[4][2];
#pragma unroll
        for (int mt = 0; mt < 2; mt++)
            ldsm_x4(a[mt][0], a[mt][1], a[mt][2], a[mt][3],
                    sA + (aRow + mt * 16) * (BSTR * 2) + (k * 16 + aCol) * 2);
#pragma unroll
        for (int nt = 0; nt < 4; nt++)
            ldsm_x2(b[nt][0], b[nt][1],
                    sB + (bRow + nt * 8) * (BSTR * 2) + (k * 16 + bCol) * 2);
#pragma unroll
        for (int mt = 0; mt < 2; mt++)
#pragma unroll
            for (int nt = 0; nt < 4; nt++)
                mma_bf16(acc[mt][nt], a[mt], b[nt]);
    }
}

// ---------------------------------------------------------------------------
// prep: Wt[w][n][k] = bf16(W_w[k][n])
// ---------------------------------------------------------------------------
__global__ void __launch_bounds__(256)
prep_w(const float* __restrict__ W0, const float* __restrict__ W1,
       const float* __restrict__ W2, const float* __restrict__ W3,
       __nv_bfloat16* __restrict__ Wt)
{
    const float* Ws[4] = {W0, W1, W2, W3};
    const float* W = Ws[blockIdx.y];
    __nv_bfloat16* dst = Wt + (size_t)blockIdx.y * 16384;
    int i = blockIdx.x * 256 + threadIdx.x;
    int n = i >> 7, k = i & 127;
    dst[n * 128 + k] = __float2bfloat16(W[k * 128 + n]);
}

// prep: split edge meta (idx / bf16 add) + CSR starts
__global__ void __launch_bounds__(256)
prep_edge(const int* __restrict__ segs, const int* __restrict__ nidx,
          const float4* __restrict__ add, int* __restrict__ eidx,
          uint2* __restrict__ eadd, int* __restrict__ start, int E, int N)
{
    int i = blockIdx.x * 256 + threadIdx.x;
    if (i >= E) return;
    float4 ad = __ldg(add + i);
    __nv_bfloat162 lo = __floats2bfloat162_rn(ad.x, ad.y);
    __nv_bfloat162 hi = __floats2bfloat162_rn(ad.z, ad.w);
    eidx[i] = __ldg(nidx + i);
    eadd[i] = make_uint2(*reinterpret_cast<uint32_t*>(&lo),
                         *reinterpret_cast<uint32_t*>(&hi));
    int b = __ldg(segs + i);
    int a = (i == 0) ? -1 : __ldg(segs + i - 1);
    for (int s = a + 1; s <= b; s++) start[s] = i;
    if (i == E - 1)
        for (int s = b + 1; s <= N; s++) start[s] = E;
}

// ---------------------------------------------------------------------------
// GEMM kernels (identical to the proven R6 configuration)
// ---------------------------------------------------------------------------
// pre: Pb = bf16(A@W + bias)   (A fp32)
__global__ void __launch_bounds__(256, 3)
gemm_pre(const float* __restrict__ A, const __nv_bfloat16* __restrict__ Wt,
         const float* __restrict__ bias, __nv_bfloat16* __restrict__ Pb, int M)
{
    extern __shared__ char smem[];
    uint32_t sA = smem_u32(smem), sB = sA + SMEM_A;
    int tid = threadIdx.x, lane = tid & 31, wid = tid >> 5;
    int wm = wid & 1, wn = wid >> 1, g = lane >> 2, tg = lane & 3;
    int tile0 = blockIdx.x * 64;

    fill_A(smem, A, tile0, M, tid);
    fill_B(smem + SMEM_A, Wt, tid);
    __syncthreads();

    float acc[2][4][4];
#pragma unroll
    for (int mt = 0; mt < 2; mt++)
#pragma unroll
        for (int nt = 0; nt < 4; nt++)
#pragma unroll
            for (int j = 0; j < 4; j++) acc[mt][nt][j] = 0.f;
    mma_tile(sA, sB, acc, lane, wm, wn);

#pragma unroll
    for (int mt = 0; mt < 2; mt++) {
        int r0 = tile0 + wm * 32 + mt * 16 + g;
#pragma unroll
        for (int nt = 0; nt < 4; nt++) {
            int c0 = wn * 32 + nt * 8 + tg * 2;
            float b0 = __ldg(bias + c0), b1 = __ldg(bias + c0 + 1);
            if (r0 < M) {
                __nv_bfloat162 o = __floats2bfloat162_rn(acc[mt][nt][0] + b0,
                                                         acc[mt][nt][1] + b1);
                *reinterpret_cast<uint32_t*>(Pb + (size_t)r0 * 128 + c0) =
                    *reinterpret_cast<uint32_t*>(&o);
            }
            if (r0 + 8 < M) {
                __nv_bfloat162 o = __floats2bfloat162_rn(acc[mt][nt][2] + b0,
                                                         acc[mt][nt][3] + b1);
                *reinterpret_cast<uint32_t*>(Pb + (size_t)(r0 + 8) * 128 + c0) =
                    *reinterpret_cast<uint32_t*>(&o);
            }
        }
    }
}

// mid: x1 = interp + poolb@W1 + bo0 (fp32 out); then Pb = bf16(x1@W2 + bb1)
__global__ void __launch_bounds__(256, 2)
gemm_mid(const __nv_bfloat16* __restrict__ poolb,
         const __nv_bfloat16* __restrict__ Wt1,
         const float* __restrict__ bo0, const float* __restrict__ interp,
         float* __restrict__ x1, const __nv_bfloat16* __restrict__ Wt2,
         const float* __restrict__ bb1, __nv_bfloat16* __restrict__ Pb, int M)
{
    extern __shared__ char smem[];
    uint32_t sA = smem_u32(smem), sB1 = sA + SMEM_A, sB2 = sB1 + SMEM_B;
    int tid = threadIdx.x, lane = tid & 31, wid = tid >> 5;
    int wm = wid & 1, wn = wid >> 1, g = lane >> 2, tg = lane & 3;
    int tile0 = blockIdx.x * 64;

    fill_Abf(smem, poolb, tile0, M, tid);
    fill_B(smem + SMEM_A, Wt1, tid);
    fill_B(smem + SMEM_A + SMEM_B, Wt2, tid);
    __syncthreads();

    float acc[2][4][4];
#pragma unroll
    for (int mt = 0; mt < 2; mt++)
#pragma unroll
        for (int nt = 0; nt < 4; nt++)
#pragma unroll
            for (int j = 0; j < 4; j++) acc[mt][nt][j] = 0.f;
    mma_tile(sA, sB1, acc, lane, wm, wn);
    __syncthreads();                        // all reads of A done before overwrite

    // Phase-A epilogue: x1 = resid + acc + bias; fp32 -> gmem, bf16 -> A smem
#pragma unroll
    for (int mt = 0; mt < 2; mt++) {
        int rl = wm * 32 + mt * 16 + g;
        int r0 = tile0 + rl;
#pragma unroll
        for (int nt = 0; nt < 4; nt++) {
            int c0 = wn * 32 + nt * 8 + tg * 2;
            float b0 = __ldg(bo0 + c0), b1 = __ldg(bo0 + c0 + 1);
            if (r0 < M) {
                float2 rv = *reinterpret_cast<const float2*>(
                    interp + (size_t)r0 * 128 + c0);
                float v0 = acc[mt][nt][0] + b0 + rv.x;
                float v1 = acc[mt][nt][1] + b1 + rv.y;
                *reinterpret_cast<float2*>(x1 + (size_t)r0 * 128 + c0) =
                    make_float2(v0, v1);
                __nv_bfloat162 o = __floats2bfloat162_rn(v0, v1);
                *reinterpret_cast<uint32_t*>(smem + rl * (BSTR * 2) + c0 * 2) =
                    *reinterpret_cast<uint32_t*>(&o);
            }
            if (r0 + 8 < M) {
                float2 rv = *reinterpret_cast<const float2*>(
                    interp + (size_t)(r0 + 8) * 128 + c0);
                float v0 = acc[mt][nt][2] + b0 + rv.x;
                float v1 = acc[mt][nt][3] + b1 + rv.y;
                *reinterpret_cast<float2*>(x1 + (size_t)(r0 + 8) * 128 + c0) =
                    make_float2(v0, v1);
                __nv_bfloat162 o = __floats2bfloat162_rn(v0, v1);
                *reinterpret_cast<uint32_t*>(smem + (rl + 8) * (BSTR * 2) + c0 * 2) =
                    *reinterpret_cast<uint32_t*>(&o);
            }
        }
    }
    __syncthreads();

    // Phase B: Pb = bf16(x1@W2 + bb1)
#pragma unroll
    for (int mt = 0; mt < 2; mt++)
#pragma unroll
        for (int nt = 0; nt < 4; nt++)
#pragma unroll
            for (int j = 0; j < 4; j++) acc[mt][nt][j] = 0.f;
    mma_tile(sA, sB2, acc, lane, wm, wn);

#pragma unroll
    for (int mt = 0; mt < 2; mt++) {
        int r0 = tile0 + wm * 32 + mt * 16 + g;
#pragma unroll
        for (int nt = 0; nt < 4; nt++) {
            int c0 = wn * 32 + nt * 8 + tg * 2;
            float b0 = __ldg(bb1 + c0), b1 = __ldg(bb1 + c0 + 1);
            if (r0 < M) {
                __nv_bfloat162 o = __floats2bfloat162_rn(acc[mt][nt][0] + b0,
                                                         acc[mt][nt][1] + b1);
                *reinterpret_cast<uint32_t*>(Pb + (size_t)r0 * 128 + c0) =
                    *reinterpret_cast<uint32_t*>(&o);
            }
            if (r0 + 8 < M) {
                __nv_bfloat162 o = __floats2bfloat162_rn(acc[mt][nt][2] + b0,
                                                         acc[mt][nt][3] + b1);
                *reinterpret_cast<uint32_t*>(Pb + (size_t)(r0 + 8) * 128 + c0) =
                    *reinterpret_cast<uint32_t*>(&o);
            }
        }
    }
}

// fin: out = (x1 + poolb@W3 + bo1) @ Wf + bf
__global__ void __launch_bounds__(256, 3)
gemm_fin(const __nv_bfloat16* __restrict__ poolb,
         const __nv_bfloat16* __restrict__ Wt3,
         const float* __restrict__ bo1, const float* __restrict__ x1,
         const float* __restrict__ Wf, const float* __restrict__ bfp,
         float* __restrict__ out, int M)
{
    extern __shared__ char smem[];
    uint32_t sA = smem_u32(smem), sB = sA + SMEM_A;
    int tid = threadIdx.x, lane = tid & 31, wid = tid >> 5;
    int wm = wid & 1, wn = wid >> 1, g = lane >> 2, tg = lane & 3;
    int tile0 = blockIdx.x * 64;

    fill_Abf(smem, poolb, tile0, M, tid);
    fill_B(smem + SMEM_A, Wt3, tid);
    __syncthreads();

    float acc[2][4][4];
#pragma unroll
    for (int mt = 0; mt < 2; mt++)
#pragma unroll
        for (int nt = 0; nt < 4; nt++)
#pragma unroll
            for (int j = 0; j < 4; j++) acc[mt][nt][j] = 0.f;
    mma_tile(sA, sB, acc, lane, wm, wn);
    __syncthreads();                        // done with A/B smem -> reuse for hp

    float* hp = reinterpret_cast<float*>(smem);   // [64][17]
#pragma unroll
    for (int mt = 0; mt < 2; mt++) {
        int rl = wm * 32 + mt * 16 + g;
        int r0 = tile0 + rl;
        float plo = 0.f, phi = 0.f;
#pragma unroll
        for (int nt = 0; nt < 4; nt++) {
            int c0 = wn * 32 + nt * 8 + tg * 2;
            float b0 = __ldg(bo1 + c0), b1 = __ldg(bo1 + c0 + 1);
            float w0 = __ldg(Wf + c0),  w1 = __ldg(Wf + c0 + 1);
            float v0 = acc[mt][nt][0] + b0, v1 = acc[mt][nt][1] + b1;
            float u0 = acc[mt][nt][2] + b0, u1 = acc[mt][nt][3] + b1;
            if (r0 < M) {
                float2 rv = *reinterpret_cast<const float2*>(
                    x1 + (size_t)r0 * 128 + c0);
                plo += (v0 + rv.x) * w0 + (v1 + rv.y) * w1;
            }
            if (r0 + 8 < M) {
                float2 rv = *reinterpret_cast<const float2*>(
                    x1 + (size_t)(r0 + 8) * 128 + c0);
                phi += (u0 + rv.x) * w0 + (u1 + rv.y) * w1;
            }
        }
        hp[rl * 17 + wn * 4 + tg] = plo;
        hp[(rl + 8) * 17 + wn * 4 + tg] = phi;
    }
    __syncthreads();
    if (tid < 64) {
        int r0 = tile0 + tid;
        if (r0 < M) {
            float s = 0.f;
#pragma unroll
            for (int j = 0; j < 16; j++) s += hp[tid * 17 + j];
            out[r0] = s + __ldg(bfp);
        }
    }
}

// ---------------------------------------------------------------------------
// Edge kernel (CSR, warp per segment, cp.async depth-4 staging): in-flight P
// rows live in SMEM (no register cost). Index ring (4 ints) prefetched 4-8
// edges ahead; add-info ring depth 2. Per edge: wait_group 3 -> LDS staged
// row -> HFMA2/HMAX2 -> issue next cp.async gather + commit. Overruns past
// the segment/E hit zero-initialized eidx (row 0) — staged but never
// consumed. Tail (<=3 edges) consumes pre-staged slots after wait_group 0.
// No atomics, no zeroing. Thread owns 4 columns (uint2 = 8 B/lane).
// ---------------------------------------------------------------------------
#define EDGE_PROC(ad, pv) do {                                               \
    __nv_bfloat162 axy = *reinterpret_cast<__nv_bfloat162*>(&(ad).x);        \
    __nv_bfloat162 azw = *reinterpret_cast<__nv_bfloat162*>(&(ad).y);        \
    __nv_bfloat162 ax = __low2bfloat162(axy),  ay = __high2bfloat162(axy);   \
    __nv_bfloat162 az = __low2bfloat162(azw),  aw = __high2bfloat162(azw);   \
    __nv_bfloat162 h0 = *reinterpret_cast<__nv_bfloat162*>(&(pv).x);         \
    __nv_bfloat162 h1 = *reinterpret_cast<__nv_bfloat162*>(&(pv).y);         \
    h0 = __hfma2(ax, wa2[0][0], h0); h1 = __hfma2(ax, wa2[0][1], h1);        \
    h0 = __hfma2(ay, wa2[1][0], h0); h1 = __hfma2(ay, wa2[1][1], h1);        \
    h0 = __hfma2(az, wa2[2][0], h0); h1 = __hfma2(az, wa2[2][1], h1);        \
    h0 = __hfma2(aw, wa2[3][0], h0); h1 = __hfma2(aw, wa2[3][1], h1);        \
    m0 = __hmax2(m0, h0); m1 = __hmax2(m1, h1);                              \
} while (0)

// One pipeline step: consume edge (t+d), issue gather for edge (t+d+4).
#define EDGE_STEP(d, ir) do {                                                \
    CP_WAIT(3);                                                              \
    uint2 pv = stage[w][d][lane];                                            \
    EDGE_PROC(a0, pv);                                                       \
    a0 = a1; a1 = __ldg(eadd + e0 + t + (d) + 2);                            \
    cpa8(sstage + (d) * 256 + lane * 8, Pr + (size_t)(ir) * 32 + lane);      \
    CP_COMMIT();                                                             \
    ir = __ldg(eidx + e0 + t + (d) + 8);                                     \
} while (0)

__global__ void __launch_bounds__(256, 2)
edge_kernel(const uint2* __restrict__ Pr, const int* __restrict__ eidx,
            const uint2* __restrict__ eadd, const int* __restrict__ start,
            const float* __restrict__ Wadd, uint2* __restrict__ poolb, int N)
{
    __shared__ uint2 stage[8][4][32];       // 8 KB: per-warp 4 slots x 256 B
    int w = threadIdx.x >> 5, lane = threadIdx.x & 31;
    int s = blockIdx.x * 8 + w;
    if (s >= N) return;
    int e0 = __ldg(start + s), en = __ldg(start + s + 1);
    int len = en - e0;

    int cb = lane * 4;
    __nv_bfloat162 wa2[4][2];
#pragma unroll
    for (int a = 0; a < 4; a++)
#pragma unroll
        for (int p = 0; p < 2; p++)
            wa2[a][p] = __floats2bfloat162_rn(__ldg(Wadd + a * 128 + cb + 2 * p),
                                              __ldg(Wadd + a * 128 + cb + 2 * p + 1));

    __nv_bfloat162 z2 = __floats2bfloat162_rn(0.f, 0.f);
    __nv_bfloat162 m0 = z2, m1 = z2;

    if (len > 0) {
        uint32_t sstage = smem_u32(&stage[w][0][0]);
        // Preamble: stage edges e0..e0+3 (reads past segment/E are safe:
        // eidx beyond E is zero-initialized -> row 0).
        int i0 = __ldg(eidx + e0);
        int i1 = __ldg(eidx + e0 + 1);
        int i2 = __ldg(eidx + e0 + 2);
        int i3 = __ldg(eidx + e0 + 3);
        cpa8(sstage +   0 + lane * 8, Pr + (size_t)i0 * 32 + lane); CP_COMMIT();
        cpa8(sstage + 256 + lane * 8, Pr + (size_t)i1 * 32 + lane); CP_COMMIT();
        cpa8(sstage + 512 + lane * 8, Pr + (size_t)i2 * 32 + lane); CP_COMMIT();
        cpa8(sstage + 768 + lane * 8, Pr + (size_t)i3 * 32 + lane); CP_COMMIT();
        i0 = __ldg(eidx + e0 + 4);
        i1 = __ldg(eidx + e0 + 5);
        i2 = __ldg(eidx + e0 + 6);
        i3 = __ldg(eidx + e0 + 7);
        uint2 a0 = __ldg(eadd + e0);
        uint2 a1 = __ldg(eadd + e0 + 1);

        int t = 0;
        while (t + 4 <= len) {
            EDGE_STEP(0, i0);
            EDGE_STEP(1, i1);
            EDGE_STEP(2, i2);
            EDGE_STEP(3, i3);
            t += 4;
        }
        // Tail: remaining edges t..len-1 are already staged (slot d = edge t+d)
        CP_WAIT(0);
        for (; t < len; t++) {
            uint2 pv = stage[w][t & 3][lane];
            EDGE_PROC(a0, pv);
            a0 = a1; a1 = __ldg(eadd + e0 + t + 2);
        }
    }

    uint2 o;
    o.x = *reinterpret_cast<uint32_t*>(&m0);
    o.y = *reinterpret_cast<uint32_t*>(&m1);
    poolb[(size_t)s * 32 + lane] = o;
}

// ---------------------------------------------------------------------------
extern "C" void kernel_launch(void* const* d_in, const int* in_sizes, int n_in,
                              void* d_out, int out_size)
{
    const float* interp = (const float*)d_in[0];
    const float* add    = (const float*)d_in[1];
    const int*   nidx   = (const int*)d_in[2];
    const int*   segs   = (const int*)d_in[3];
    const float* Wb0 = (const float*)d_in[4];
    const float* bb0 = (const float*)d_in[5];
    const float* Wo0 = (const float*)d_in[6];
    const float* bo0 = (const float*)d_in[7];
    const float* Wb1 = (const float*)d_in[8];
    const float* bb1 = (const float*)d_in[9];
    const float* Wo1 = (const float*)d_in[10];
    const float* bo1 = (const float*)d_in[11];
    const float* Wf  = (const float*)d_in[12];
    const float* bf  = (const float*)d_in[13];
    float* out = (float*)d_out;

    int N = in_sizes[0] / 128;
    int E = in_sizes[2];

    __nv_bfloat16 *P, *poolb, *Wt;
    float *x1;
    int *eidx, *start;
    uint2* eadd;
    cudaGetSymbolAddress((void**)&P, g_P);
    cudaGetSymbolAddress((void**)&poolb, g_poolb);
    cudaGetSymbolAddress((void**)&x1, g_x1);
    cudaGetSymbolAddress((void**)&Wt, g_Wt);
    cudaGetSymbolAddress((void**)&eidx, g_eidx);
    cudaGetSymbolAddress((void**)&eadd, g_eadd);
    cudaGetSymbolAddress((void**)&start, g_start);

    cudaFuncSetAttribute(gemm_pre, cudaFuncAttributeMaxDynamicSharedMemorySize, SMEM_PF);
    cudaFuncSetAttribute(gemm_mid, cudaFuncAttributeMaxDynamicSharedMemorySize, SMEM_MID);
    cudaFuncSetAttribute(gemm_fin, cudaFuncAttributeMaxDynamicSharedMemorySize, SMEM_PF);

    int gtiles = (N + 63) / 64;
    int sgrid = (N + 7) / 8;

    prep_w<<<dim3(64, 4), 256>>>(Wb0, Wo0, Wb1, Wo1, Wt);
    prep_edge<<<(E + 255) / 256, 256>>>(segs, nidx, (const float4*)add,
                                        eidx, eadd, start, E, N);

    // Block 0
    gemm_pre<<<gtiles, 256, SMEM_PF>>>(interp, Wt + 0 * 16384, bb0, P, N);
    edge_kernel<<<sgrid, 256>>>((const uint2*)P, eidx, eadd, start,
                                Wb0 + 128 * 128, (uint2*)poolb, N);
    // Block-0 projection + Block-1 pre-edge GEMM fused
    gemm_mid<<<gtiles, 256, SMEM_MID>>>(poolb, Wt + 1 * 16384, bo0, interp, x1,
                                        Wt + 2 * 16384, bb1, P, N);
    edge_kernel<<<sgrid, 256>>>((const uint2*)P, eidx, eadd, start,
                                Wb1 + 128 * 128, (uint2*)poolb, N);
    // Block-1 projection + final head fused
    gemm_fin<<<gtiles, 256, SMEM_PF>>>(poolb, Wt + 3 * 16384, bo1, x1, Wf, bf,
                                       out, N);
}

// round 13
// speedup vs baseline: 1.7956x; 1.2966x over previous
#include <cuda_runtime.h>
#include <cuda_bf16.h>
#include <cstdint>

// ---------------------------------------------------------------------------
// Problem shape (fixed by dataset): N=50000, E=1.6M, D=128, A=4, H=128
// ---------------------------------------------------------------------------
#define NMAX 50048          // 782 tiles of 64
#define EMAX 1700000
#define DDIM 128

__device__ __nv_bfloat16 g_P[(size_t)NMAX * DDIM];      // bf16 activations (pre-edge)
__device__ __nv_bfloat16 g_poolb[(size_t)NMAX * DDIM];  // bf16 pooled output
__device__ float g_x1  [(size_t)NMAX * DDIM];           // fp32 residual stream
__device__ __nv_bfloat16 g_Wt[4 * 128 * 128];           // transposed bf16 weights
__device__ uint4 g_edge[EMAX];                          // packed {idx, bf16 add x4, 0}
__device__ int   g_start[NMAX + 1];                     // CSR segment starts

// ---------------------------------------------------------------------------
// helpers
// ---------------------------------------------------------------------------
__device__ __forceinline__ uint32_t smem_u32(const void* p) {
    uint32_t a;
    asm("{ .reg .u64 t; cvta.to.shared.u64 t, %1; cvt.u32.u64 %0, t; }"
        : "=r"(a) : "l"(p));
    return a;
}
__device__ __forceinline__ void ldsm_x4(uint32_t& r0, uint32_t& r1,
                                        uint32_t& r2, uint32_t& r3, uint32_t a) {
    asm volatile("ldmatrix.sync.aligned.m8n8.x4.shared.b16 {%0,%1,%2,%3}, [%4];"
                 : "=r"(r0), "=r"(r1), "=r"(r2), "=r"(r3) : "r"(a));
}
__device__ __forceinline__ void ldsm_x2(uint32_t& r0, uint32_t& r1, uint32_t a) {
    asm volatile("ldmatrix.sync.aligned.m8n8.x2.shared.b16 {%0,%1}, [%2];"
                 : "=r"(r0), "=r"(r1) : "r"(a));
}
__device__ __forceinline__ void mma_bf16(float* c, const uint32_t* a, const uint32_t* b) {
    asm volatile(
        "mma.sync.aligned.m16n8k16.row.col.f32.bf16.bf16.f32 "
        "{%0,%1,%2,%3}, {%4,%5,%6,%7}, {%8,%9}, {%0,%1,%2,%3};"
        : "+f"(c[0]), "+f"(c[1]), "+f"(c[2]), "+f"(c[3])
        : "r"(a[0]), "r"(a[1]), "r"(a[2]), "r"(a[3]), "r"(b[0]), "r"(b[1]));
}

// ---------------------------------------------------------------------------
// Tiling constants: CTA = 64 rows x 128 cols, 8 warps (2 m x 4 n), K=128
// ---------------------------------------------------------------------------
#define BSTR 136                              // bf16 elems per smem row (pad 8)
static constexpr int SMEM_A  = 64 * BSTR * 2;    // 17408
static constexpr int SMEM_B  = 128 * BSTR * 2;   // 34816
static constexpr int SMEM_PF = SMEM_A + SMEM_B;          // 52224 (pre/fin)
static constexpr int SMEM_MID = SMEM_A + 2 * SMEM_B;     // 87040 (mid)

// A tile fill: 64x128 fp32 -> bf16 smem
__device__ __forceinline__ void fill_A(char* smem, const float* __restrict__ A,
                                       int tile0, int M, int tid) {
#pragma unroll
    for (int it = 0; it < 8; it++) {
        int p = it * 256 + tid;               // 0..2047
        int r = p >> 5, c = p & 31;
        int gr = tile0 + r;
        float4 v = make_float4(0.f, 0.f, 0.f, 0.f);
        if (gr < M) v = __ldg(reinterpret_cast<const float4*>(A + (size_t)gr * 128) + c);
        __nv_bfloat162 lo = __floats2bfloat162_rn(v.x, v.y);
        __nv_bfloat162 hi = __floats2bfloat162_rn(v.z, v.w);
        uint2 o = make_uint2(*reinterpret_cast<uint32_t*>(&lo),
                             *reinterpret_cast<uint32_t*>(&hi));
        *reinterpret_cast<uint2*>(smem + r * (BSTR * 2) + c * 8) = o;
    }
}
// A tile fill from bf16 source (straight copy)
__device__ __forceinline__ void fill_Abf(char* smem, const __nv_bfloat16* __restrict__ A,
                                         int tile0, int M, int tid) {
    const uint4* src = reinterpret_cast<const uint4*>(A + (size_t)tile0 * 128);
#pragma unroll
    for (int it = 0; it < 4; it++) {
        int p = it * 256 + tid;               // 0..1023
        int r = p >> 4, c = p & 15;
        uint4 v = make_uint4(0, 0, 0, 0);
        if (tile0 + r < M) v = __ldg(src + p);
        *reinterpret_cast<uint4*>(smem + r * (BSTR * 2) + c * 16) = v;
    }
}
// B tile fill: 128x128 bf16 (pre-transposed) -> smem, uint4 copies
__device__ __forceinline__ void fill_B(char* dst, const __nv_bfloat16* __restrict__ Wt,
                                       int tid) {
    const uint4* src = reinterpret_cast<const uint4*>(Wt);
#pragma unroll
    for (int it = 0; it < 8; it++) {
        int p = it * 256 + tid;               // 0..2047
        int n = p >> 4, c = p & 15;
        *reinterpret_cast<uint4*>(dst + n * (BSTR * 2) + c * 16) = src[p];
    }
}
// MMA core: acc[2][4][4] over 64x128 tile
__device__ __forceinline__ void mma_tile(uint32_t sA, uint32_t sB,
                                         float acc[2][4][4], int lane,
                                         int wm, int wn) {
    int aRow = wm * 32 + (lane & 15);
    int aCol = (lane >> 4) * 8;
    int bRow = wn * 32 + (lane & 7);
    int bCol = ((lane >> 3) & 1) * 8;
#pragma unroll
    for (int k = 0; k < 8; k++) {
        uint32_t a[2][4], b[4][2];
#pragma unroll
        for (int mt = 0; mt < 2; mt++)
            ldsm_x4(a[mt][0], a[mt][1], a[mt][2], a[mt][3],
                    sA + (aRow + mt * 16) * (BSTR * 2) + (k * 16 + aCol) * 2);
#pragma unroll
        for (int nt = 0; nt < 4; nt++)
            ldsm_x2(b[nt][0], b[nt][1],
                    sB + (bRow + nt * 8) * (BSTR * 2) + (k * 16 + bCol) * 2);
#pragma unroll
        for (int mt = 0; mt < 2; mt++)
#pragma unroll
            for (int nt = 0; nt < 4; nt++)
                mma_bf16(acc[mt][nt], a[mt], b[nt]);
    }
}

// ---------------------------------------------------------------------------
// prep: Wt[w][n][k] = bf16(W_w[k][n])
// ---------------------------------------------------------------------------
__global__ void __launch_bounds__(256)
prep_w(const float* __restrict__ W0, const float* __restrict__ W1,
       const float* __restrict__ W2, const float* __restrict__ W3,
       __nv_bfloat16* __restrict__ Wt)
{
    const float* Ws[4] = {W0, W1, W2, W3};
    const float* W = Ws[blockIdx.y];
    __nv_bfloat16* dst = Wt + (size_t)blockIdx.y * 16384;
    int i = blockIdx.x * 256 + threadIdx.x;
    int n = i >> 7, k = i & 127;
    dst[n * 128 + k] = __float2bfloat16(W[k * 128 + n]);
}

// prep: pack per-edge meta {idx, bf16(add.xy), bf16(add.zw), 0} + CSR starts
__global__ void __launch_bounds__(256)
prep_edge(const int* __restrict__ segs, const int* __restrict__ nidx,
          const float4* __restrict__ add, uint4* __restrict__ em,
          int* __restrict__ start, int E, int N)
{
    int i = blockIdx.x * 256 + threadIdx.x;
    if (i >= E) return;
    float4 ad = __ldg(add + i);
    __nv_bfloat162 lo = __floats2bfloat162_rn(ad.x, ad.y);
    __nv_bfloat162 hi = __floats2bfloat162_rn(ad.z, ad.w);
    em[i] = make_uint4((uint32_t)__ldg(nidx + i),
                       *reinterpret_cast<uint32_t*>(&lo),
                       *reinterpret_cast<uint32_t*>(&hi), 0u);
    int b = __ldg(segs + i);
    int a = (i == 0) ? -1 : __ldg(segs + i - 1);
    for (int s = a + 1; s <= b; s++) start[s] = i;
    if (i == E - 1)
        for (int s = b + 1; s <= N; s++) start[s] = E;
}

// ---------------------------------------------------------------------------
// GEMM kernels (identical to the proven R6 configuration)
// ---------------------------------------------------------------------------
// pre: Pb = bf16(A@W + bias)   (A fp32)
__global__ void __launch_bounds__(256, 3)
gemm_pre(const float* __restrict__ A, const __nv_bfloat16* __restrict__ Wt,
         const float* __restrict__ bias, __nv_bfloat16* __restrict__ Pb, int M)
{
    extern __shared__ char smem[];
    uint32_t sA = smem_u32(smem), sB = sA + SMEM_A;
    int tid = threadIdx.x, lane = tid & 31, wid = tid >> 5;
    int wm = wid & 1, wn = wid >> 1, g = lane >> 2, tg = lane & 3;
    int tile0 = blockIdx.x * 64;

    fill_A(smem, A, tile0, M, tid);
    fill_B(smem + SMEM_A, Wt, tid);
    __syncthreads();

    float acc[2][4][4];
#pragma unroll
    for (int mt = 0; mt < 2; mt++)
#pragma unroll
        for (int nt = 0; nt < 4; nt++)
#pragma unroll
            for (int j = 0; j < 4; j++) acc[mt][nt][j] = 0.f;
    mma_tile(sA, sB, acc, lane, wm, wn);

#pragma unroll
    for (int mt = 0; mt < 2; mt++) {
        int r0 = tile0 + wm * 32 + mt * 16 + g;
#pragma unroll
        for (int nt = 0; nt < 4; nt++) {
            int c0 = wn * 32 + nt * 8 + tg * 2;
            float b0 = __ldg(bias + c0), b1 = __ldg(bias + c0 + 1);
            if (r0 < M) {
                __nv_bfloat162 o = __floats2bfloat162_rn(acc[mt][nt][0] + b0,
                                                         acc[mt][nt][1] + b1);
                *reinterpret_cast<uint32_t*>(Pb + (size_t)r0 * 128 + c0) =
                    *reinterpret_cast<uint32_t*>(&o);
            }
            if (r0 + 8 < M) {
                __nv_bfloat162 o = __floats2bfloat162_rn(acc[mt][nt][2] + b0,
                                                         acc[mt][nt][3] + b1);
                *reinterpret_cast<uint32_t*>(Pb + (size_t)(r0 + 8) * 128 + c0) =
                    *reinterpret_cast<uint32_t*>(&o);
            }
        }
    }
}

// mid: x1 = interp + poolb@W1 + bo0 (fp32 out); then Pb = bf16(x1@W2 + bb1)
__global__ void __launch_bounds__(256, 2)
gemm_mid(const __nv_bfloat16* __restrict__ poolb,
         const __nv_bfloat16* __restrict__ Wt1,
         const float* __restrict__ bo0, const float* __restrict__ interp,
         float* __restrict__ x1, const __nv_bfloat16* __restrict__ Wt2,
         const float* __restrict__ bb1, __nv_bfloat16* __restrict__ Pb, int M)
{
    extern __shared__ char smem[];
    uint32_t sA = smem_u32(smem), sB1 = sA + SMEM_A, sB2 = sB1 + SMEM_B;
    int tid = threadIdx.x, lane = tid & 31, wid = tid >> 5;
    int wm = wid & 1, wn = wid >> 1, g = lane >> 2, tg = lane & 3;
    int tile0 = blockIdx.x * 64;

    fill_Abf(smem, poolb, tile0, M, tid);
    fill_B(smem + SMEM_A, Wt1, tid);
    fill_B(smem + SMEM_A + SMEM_B, Wt2, tid);
    __syncthreads();

    float acc[2][4][4];
#pragma unroll
    for (int mt = 0; mt < 2; mt++)
#pragma unroll
        for (int nt = 0; nt < 4; nt++)
#pragma unroll
            for (int j = 0; j < 4; j++) acc[mt][nt][j] = 0.f;
    mma_tile(sA, sB1, acc, lane, wm, wn);
    __syncthreads();                        // all reads of A done before overwrite

    // Phase-A epilogue: x1 = resid + acc + bias; fp32 -> gmem, bf16 -> A smem
#pragma unroll
    for (int mt = 0; mt < 2; mt++) {
        int rl = wm * 32 + mt * 16 + g;
        int r0 = tile0 + rl;
#pragma unroll
        for (int nt = 0; nt < 4; nt++) {
            int c0 = wn * 32 + nt * 8 + tg * 2;
            float b0 = __ldg(bo0 + c0), b1 = __ldg(bo0 + c0 + 1);
            if (r0 < M) {
                float2 rv = *reinterpret_cast<const float2*>(
                    interp + (size_t)r0 * 128 + c0);
                float v0 = acc[mt][nt][0] + b0 + rv.x;
                float v1 = acc[mt][nt][1] + b1 + rv.y;
                *reinterpret_cast<float2*>(x1 + (size_t)r0 * 128 + c0) =
                    make_float2(v0, v1);
                __nv_bfloat162 o = __floats2bfloat162_rn(v0, v1);
                *reinterpret_cast<uint32_t*>(smem + rl * (BSTR * 2) + c0 * 2) =
                    *reinterpret_cast<uint32_t*>(&o);
            }
            if (r0 + 8 < M) {
                float2 rv = *reinterpret_cast<const float2*>(
                    interp + (size_t)(r0 + 8) * 128 + c0);
                float v0 = acc[mt][nt][2] + b0 + rv.x;
                float v1 = acc[mt][nt][3] + b1 + rv.y;
                *reinterpret_cast<float2*>(x1 + (size_t)(r0 + 8) * 128 + c0) =
                    make_float2(v0, v1);
                __nv_bfloat162 o = __floats2bfloat162_rn(v0, v1);
                *reinterpret_cast<uint32_t*>(smem + (rl + 8) * (BSTR * 2) + c0 * 2) =
                    *reinterpret_cast<uint32_t*>(&o);
            }
        }
    }
    __syncthreads();

    // Phase B: Pb = bf16(x1@W2 + bb1)
#pragma unroll
    for (int mt = 0; mt < 2; mt++)
#pragma unroll
        for (int nt = 0; nt < 4; nt++)
#pragma unroll
            for (int j = 0; j < 4; j++) acc[mt][nt][j] = 0.f;
    mma_tile(sA, sB2, acc, lane, wm, wn);

#pragma unroll
    for (int mt = 0; mt < 2; mt++) {
        int r0 = tile0 + wm * 32 + mt * 16 + g;
#pragma unroll
        for (int nt = 0; nt < 4; nt++) {
            int c0 = wn * 32 + nt * 8 + tg * 2;
            float b0 = __ldg(bb1 + c0), b1 = __ldg(bb1 + c0 + 1);
            if (r0 < M) {
                __nv_bfloat162 o = __floats2bfloat162_rn(acc[mt][nt][0] + b0,
                                                         acc[mt][nt][1] + b1);
                *reinterpret_cast<uint32_t*>(Pb + (size_t)r0 * 128 + c0) =
                    *reinterpret_cast<uint32_t*>(&o);
            }
            if (r0 + 8 < M) {
                __nv_bfloat162 o = __floats2bfloat162_rn(acc[mt][nt][2] + b0,
                                                         acc[mt][nt][3] + b1);
                *reinterpret_cast<uint32_t*>(Pb + (size_t)(r0 + 8) * 128 + c0) =
                    *reinterpret_cast<uint32_t*>(&o);
            }
        }
    }
}

// fin: out = (x1 + poolb@W3 + bo1) @ Wf + bf
__global__ void __launch_bounds__(256, 3)
gemm_fin(const __nv_bfloat16* __restrict__ poolb,
         const __nv_bfloat16* __restrict__ Wt3,
         const float* __restrict__ bo1, const float* __restrict__ x1,
         const float* __restrict__ Wf, const float* __restrict__ bfp,
         float* __restrict__ out, int M)
{
    extern __shared__ char smem[];
    uint32_t sA = smem_u32(smem), sB = sA + SMEM_A;
    int tid = threadIdx.x, lane = tid & 31, wid = tid >> 5;
    int wm = wid & 1, wn = wid >> 1, g = lane >> 2, tg = lane & 3;
    int tile0 = blockIdx.x * 64;

    fill_Abf(smem, poolb, tile0, M, tid);
    fill_B(smem + SMEM_A, Wt3, tid);
    __syncthreads();

    float acc[2][4][4];
#pragma unroll
    for (int mt = 0; mt < 2; mt++)
#pragma unroll
        for (int nt = 0; nt < 4; nt++)
#pragma unroll
            for (int j = 0; j < 4; j++) acc[mt][nt][j] = 0.f;
    mma_tile(sA, sB, acc, lane, wm, wn);
    __syncthreads();                        // done with A/B smem -> reuse for hp

    float* hp = reinterpret_cast<float*>(smem);   // [64][17]
#pragma unroll
    for (int mt = 0; mt < 2; mt++) {
        int rl = wm * 32 + mt * 16 + g;
        int r0 = tile0 + rl;
        float plo = 0.f, phi = 0.f;
#pragma unroll
        for (int nt = 0; nt < 4; nt++) {
            int c0 = wn * 32 + nt * 8 + tg * 2;
            float b0 = __ldg(bo1 + c0), b1 = __ldg(bo1 + c0 + 1);
            float w0 = __ldg(Wf + c0),  w1 = __ldg(Wf + c0 + 1);
            float v0 = acc[mt][nt][0] + b0, v1 = acc[mt][nt][1] + b1;
            float u0 = acc[mt][nt][2] + b0, u1 = acc[mt][nt][3] + b1;
            if (r0 < M) {
                float2 rv = *reinterpret_cast<const float2*>(
                    x1 + (size_t)r0 * 128 + c0);
                plo += (v0 + rv.x) * w0 + (v1 + rv.y) * w1;
            }
            if (r0 + 8 < M) {
                float2 rv = *reinterpret_cast<const float2*>(
                    x1 + (size_t)(r0 + 8) * 128 + c0);
                phi += (u0 + rv.x) * w0 + (u1 + rv.y) * w1;
            }
        }
        hp[rl * 17 + wn * 4 + tg] = plo;
        hp[(rl + 8) * 17 + wn * 4 + tg] = phi;
    }
    __syncthreads();
    if (tid < 64) {
        int r0 = tile0 + tid;
        if (r0 < M) {
            float s = 0.f;
#pragma unroll
            for (int j = 0; j < 16; j++) s += hp[tid * 17 + j];
            out[r0] = s + __ldg(bfp);
        }
    }
}

// ---------------------------------------------------------------------------
// Edge kernel (CSR, warp per segment, meta-ahead pipeline): the next edge's
// meta uint4 loads BEFORE the current edge's P gather, so the two ~250-cycle
// L2 hits overlap instead of chaining (one extra uint4 of registers, no
// clamps, no rings). h = P[idx] + add@Wadd (HFMA2); running max (HMAX2,
// zero-init = relu fold); plain uint2 store. No atomics, no zeroing.
// Thread owns 4 columns.
// ---------------------------------------------------------------------------
#define EDGE_PROC(md, pv) do {                                               \
    __nv_bfloat162 axy = *reinterpret_cast<__nv_bfloat162*>(&(md).y);        \
    __nv_bfloat162 azw = *reinterpret_cast<__nv_bfloat162*>(&(md).z);        \
    __nv_bfloat162 ax = __low2bfloat162(axy),  ay = __high2bfloat162(axy);   \
    __nv_bfloat162 az = __low2bfloat162(azw),  aw = __high2bfloat162(azw);   \
    __nv_bfloat162 h0 = *reinterpret_cast<__nv_bfloat162*>(&(pv).x);         \
    __nv_bfloat162 h1 = *reinterpret_cast<__nv_bfloat162*>(&(pv).y);         \
    h0 = __hfma2(ax, wa2[0][0], h0); h1 = __hfma2(ax, wa2[0][1], h1);        \
    h0 = __hfma2(ay, wa2[1][0], h0); h1 = __hfma2(ay, wa2[1][1], h1);        \
    h0 = __hfma2(az, wa2[2][0], h0); h1 = __hfma2(az, wa2[2][1], h1);        \
    h0 = __hfma2(aw, wa2[3][0], h0); h1 = __hfma2(aw, wa2[3][1], h1);        \
    m0 = __hmax2(m0, h0); m1 = __hmax2(m1, h1);                              \
} while (0)

__global__ void __launch_bounds__(256)
edge_kernel(const uint2* __restrict__ Pr, const uint4* __restrict__ em,
            const int* __restrict__ start, const float* __restrict__ Wadd,
            uint2* __restrict__ poolb, int N)
{
    int s = blockIdx.x * 8 + (threadIdx.x >> 5);
    if (s >= N) return;
    int lane = threadIdx.x & 31;
    int e0 = __ldg(start + s);
    int en = __ldg(start + s + 1);
    int len = en - e0;

    int cb = lane * 4;
    __nv_bfloat162 wa2[4][2];
#pragma unroll
    for (int a = 0; a < 4; a++)
#pragma unroll
        for (int p = 0; p < 2; p++)
            wa2[a][p] = __floats2bfloat162_rn(__ldg(Wadd + a * 128 + cb + 2 * p),
                                              __ldg(Wadd + a * 128 + cb + 2 * p + 1));

    __nv_bfloat162 z2 = __floats2bfloat162_rn(0.f, 0.f);
    __nv_bfloat162 m0 = z2, m1 = z2;

    if (len > 0) {
        uint4 md = __ldg(em + e0);
#pragma unroll 2
        for (int t = 1; t < len; t++) {
            uint4 mdn = __ldg(em + e0 + t);                 // next meta first
            uint2 pv  = __ldg(Pr + (size_t)md.x * 32 + lane);
            EDGE_PROC(md, pv);
            md = mdn;
        }
        uint2 pv = __ldg(Pr + (size_t)md.x * 32 + lane);    // last edge
        EDGE_PROC(md, pv);
    }

    uint2 o;
    o.x = *reinterpret_cast<uint32_t*>(&m0);
    o.y = *reinterpret_cast<uint32_t*>(&m1);
    poolb[(size_t)s * 32 + lane] = o;
}

// ---------------------------------------------------------------------------
extern "C" void kernel_launch(void* const* d_in, const int* in_sizes, int n_in,
                              void* d_out, int out_size)
{
    const float* interp = (const float*)d_in[0];
    const float* add    = (const float*)d_in[1];
    const int*   nidx   = (const int*)d_in[2];
    const int*   segs   = (const int*)d_in[3];
    const float* Wb0 = (const float*)d_in[4];
    const float* bb0 = (const float*)d_in[5];
    const float* Wo0 = (const float*)d_in[6];
    const float* bo0 = (const float*)d_in[7];
    const float* Wb1 = (const float*)d_in[8];
    const float* bb1 = (const float*)d_in[9];
    const float* Wo1 = (const float*)d_in[10];
    const float* bo1 = (const float*)d_in[11];
    const float* Wf  = (const float*)d_in[12];
    const float* bf  = (const float*)d_in[13];
    float* out = (float*)d_out;

    int N = in_sizes[0] / 128;
    int E = in_sizes[2];

    __nv_bfloat16 *P, *poolb, *Wt;
    float *x1;
    uint4* em;
    int* start;
    cudaGetSymbolAddress((void**)&P, g_P);
    cudaGetSymbolAddress((void**)&poolb, g_poolb);
    cudaGetSymbolAddress((void**)&x1, g_x1);
    cudaGetSymbolAddress((void**)&Wt, g_Wt);
    cudaGetSymbolAddress((void**)&em, g_edge);
    cudaGetSymbolAddress((void**)&start, g_start);

    cudaFuncSetAttribute(gemm_pre, cudaFuncAttributeMaxDynamicSharedMemorySize, SMEM_PF);
    cudaFuncSetAttribute(gemm_mid, cudaFuncAttributeMaxDynamicSharedMemorySize, SMEM_MID);
    cudaFuncSetAttribute(gemm_fin, cudaFuncAttributeMaxDynamicSharedMemorySize, SMEM_PF);

    int gtiles = (N + 63) / 64;
    int sgrid = (N + 7) / 8;

    prep_w<<<dim3(64, 4), 256>>>(Wb0, Wo0, Wb1, Wo1, Wt);
    prep_edge<<<(E + 255) / 256, 256>>>(segs, nidx, (const float4*)add, em,
                                        start, E, N);

    // Block 0
    gemm_pre<<<gtiles, 256, SMEM_PF>>>(interp, Wt + 0 * 16384, bb0, P, N);
    edge_kernel<<<sgrid, 256>>>((const uint2*)P, em, start, Wb0 + 128 * 128,
                                (uint2*)poolb, N);
    // Block-0 projection + Block-1 pre-edge GEMM fused
    gemm_mid<<<gtiles, 256, SMEM_MID>>>(poolb, Wt + 1 * 16384, bo0, interp, x1,
                                        Wt + 2 * 16384, bb1, P, N);
    edge_kernel<<<sgrid, 256>>>((const uint2*)P, em, start, Wb1 + 128 * 128,
                                (uint2*)poolb, N);
    // Block-1 projection + final head fused
    gemm_fin<<<gtiles, 256, SMEM_PF>>>(poolb, Wt + 3 * 16384, bo1, x1, Wf, bf,
                                       out, N);
}

// round 15
// speedup vs baseline: 1.8756x; 1.0445x over previous
#include <cuda_runtime.h>
#include <cuda_bf16.h>
#include <cstdint>

// ---------------------------------------------------------------------------
// Problem shape (fixed by dataset): N=50000, E=1.6M, D=128, A=4, H=128
// ---------------------------------------------------------------------------
#define NMAX 50048          // 782 tiles of 64
#define EMAX 1700000
#define DDIM 128

__device__ __nv_bfloat16 g_P[(size_t)NMAX * DDIM];      // bf16 activations (pre-edge)
__device__ __nv_bfloat16 g_poolb[(size_t)NMAX * DDIM];  // bf16 pooled output
__device__ float g_x1  [(size_t)NMAX * DDIM];           // fp32 residual stream
__device__ __nv_bfloat16 g_Wt[4 * 128 * 128];           // transposed bf16 weights
__device__ uint4 g_edge[EMAX];                          // packed {idx, bf16 add x4, 0}
__device__ int   g_start[NMAX + 1];                     // CSR segment starts

// ---------------------------------------------------------------------------
// helpers
// ---------------------------------------------------------------------------
__device__ __forceinline__ uint32_t smem_u32(const void* p) {
    uint32_t a;
    asm("{ .reg .u64 t; cvta.to.shared.u64 t, %1; cvt.u32.u64 %0, t; }"
        : "=r"(a) : "l"(p));
    return a;
}
__device__ __forceinline__ void ldsm_x4(uint32_t& r0, uint32_t& r1,
                                        uint32_t& r2, uint32_t& r3, uint32_t a) {
    asm volatile("ldmatrix.sync.aligned.m8n8.x4.shared.b16 {%0,%1,%2,%3}, [%4];"
                 : "=r"(r0), "=r"(r1), "=r"(r2), "=r"(r3) : "r"(a));
}
__device__ __forceinline__ void ldsm_x2(uint32_t& r0, uint32_t& r1, uint32_t a) {
    asm volatile("ldmatrix.sync.aligned.m8n8.x2.shared.b16 {%0,%1}, [%2];"
                 : "=r"(r0), "=r"(r1) : "r"(a));
}
__device__ __forceinline__ void mma_bf16(float* c, const uint32_t* a, const uint32_t* b) {
    asm volatile(
        "mma.sync.aligned.m16n8k16.row.col.f32.bf16.bf16.f32 "
        "{%0,%1,%2,%3}, {%4,%5,%6,%7}, {%8,%9}, {%0,%1,%2,%3};"
        : "+f"(c[0]), "+f"(c[1]), "+f"(c[2]), "+f"(c[3])
        : "r"(a[0]), "r"(a[1]), "r"(a[2]), "r"(a[3]), "r"(b[0]), "r"(b[1]));
}

// ---------------------------------------------------------------------------
// Tiling constants: CTA = 64 rows x 128 cols, 8 warps (2 m x 4 n), K=128
// ---------------------------------------------------------------------------
#define BSTR 136                              // bf16 elems per smem row (pad 8)
static constexpr int SMEM_A  = 64 * BSTR * 2;    // 17408
static constexpr int SMEM_B  = 128 * BSTR * 2;   // 34816
static constexpr int SMEM_PF = SMEM_A + SMEM_B;          // 52224 (pre/fin)
static constexpr int SMEM_MID = SMEM_A + 2 * SMEM_B;     // 87040 (mid)

// A tile fill: 64x128 fp32 -> bf16 smem
__device__ __forceinline__ void fill_A(char* smem, const float* __restrict__ A,
                                       int tile0, int M, int tid) {
#pragma unroll
    for (int it = 0; it < 8; it++) {
        int p = it * 256 + tid;               // 0..2047
        int r = p >> 5, c = p & 31;
        int gr = tile0 + r;
        float4 v = make_float4(0.f, 0.f, 0.f, 0.f);
        if (gr < M) v = __ldg(reinterpret_cast<const float4*>(A + (size_t)gr * 128) + c);
        __nv_bfloat162 lo = __floats2bfloat162_rn(v.x, v.y);
        __nv_bfloat162 hi = __floats2bfloat162_rn(v.z, v.w);
        uint2 o = make_uint2(*reinterpret_cast<uint32_t*>(&lo),
                             *reinterpret_cast<uint32_t*>(&hi));
        *reinterpret_cast<uint2*>(smem + r * (BSTR * 2) + c * 8) = o;
    }
}
// A tile fill from bf16 source (straight copy)
__device__ __forceinline__ void fill_Abf(char* smem, const __nv_bfloat16* __restrict__ A,
                                         int tile0, int M, int tid) {
    const uint4* src = reinterpret_cast<const uint4*>(A + (size_t)tile0 * 128);
#pragma unroll
    for (int it = 0; it < 4; it++) {
        int p = it * 256 + tid;               // 0..1023
        int r = p >> 4, c = p & 15;
        uint4 v = make_uint4(0, 0, 0, 0);
        if (tile0 + r < M) v = __ldg(src + p);
        *reinterpret_cast<uint4*>(smem + r * (BSTR * 2) + c * 16) = v;
    }
}
// B tile fill: 128x128 bf16 (pre-transposed) -> smem, uint4 copies
__device__ __forceinline__ void fill_B(char* dst, const __nv_bfloat16* __restrict__ Wt,
                                       int tid) {
    const uint4* src = reinterpret_cast<const uint4*>(Wt);
#pragma unroll
    for (int it = 0; it < 8; it++) {
        int p = it * 256 + tid;               // 0..2047
        int n = p >> 4, c = p & 15;
        *reinterpret_cast<uint4*>(dst + n * (BSTR * 2) + c * 16) = src[p];
    }
}
// MMA core: acc[2][4][4] over 64x128 tile
__device__ __forceinline__ void mma_tile(uint32_t sA, uint32_t sB,
                                         float acc[2][4][4], int lane,
                                         int wm, int wn) {
    int aRow = wm * 32 + (lane & 15);
    int aCol = (lane >> 4) * 8;
    int bRow = wn * 32 + (lane & 7);
    int bCol = ((lane >> 3) & 1) * 8;
#pragma unroll
    for (int k = 0; k < 8; k++) {
        uint32_t a[2][4], b[4][2];
#pragma unroll
        for (int mt = 0; mt < 2; mt++)
            ldsm_x4(a[mt][0], a[mt][1], a[mt][2], a[mt][3],
                    sA + (aRow + mt * 16) * (BSTR * 2) + (k * 16 + aCol) * 2);
#pragma unroll
        for (int nt = 0; nt < 4; nt++)
            ldsm_x2(b[nt][0], b[nt][1],
                    sB + (bRow + nt * 8) * (BSTR * 2) + (k * 16 + bCol) * 2);
#pragma unroll
        for (int mt = 0; mt < 2; mt++)
#pragma unroll
            for (int nt = 0; nt < 4; nt++)
                mma_bf16(acc[mt][nt], a[mt], b[nt]);
    }
}

// ---------------------------------------------------------------------------
// prep: Wt[w][n][k] = bf16(W_w[k][n])
// ---------------------------------------------------------------------------
__global__ void __launch_bounds__(256)
prep_w(const float* __restrict__ W0, const float* __restrict__ W1,
       const float* __restrict__ W2, const float* __restrict__ W3,
       __nv_bfloat16* __restrict__ Wt)
{
    const float* Ws[4] = {W0, W1, W2, W3};
    const float* W = Ws[blockIdx.y];
    __nv_bfloat16* dst = Wt + (size_t)blockIdx.y * 16384;
    int i = blockIdx.x * 256 + threadIdx.x;
    int n = i >> 7, k = i & 127;
    dst[n * 128 + k] = __float2bfloat16(W[k * 128 + n]);
}

// prep: pack per-edge meta {idx, bf16(add.xy), bf16(add.zw), 0} + CSR starts
__global__ void __launch_bounds__(256)
prep_edge(const int* __restrict__ segs, const int* __restrict__ nidx,
          const float4* __restrict__ add, uint4* __restrict__ em,
          int* __restrict__ start, int E, int N)
{
    int i = blockIdx.x * 256 + threadIdx.x;
    if (i >= E) return;
    float4 ad = __ldg(add + i);
    __nv_bfloat162 lo = __floats2bfloat162_rn(ad.x, ad.y);
    __nv_bfloat162 hi = __floats2bfloat162_rn(ad.z, ad.w);
    em[i] = make_uint4((uint32_t)__ldg(nidx + i),
                       *reinterpret_cast<uint32_t*>(&lo),
                       *reinterpret_cast<uint32_t*>(&hi), 0u);
    int b = __ldg(segs + i);
    int a = (i == 0) ? -1 : __ldg(segs + i - 1);
    for (int s = a + 1; s <= b; s++) start[s] = i;
    if (i == E - 1)
        for (int s = b + 1; s <= N; s++) start[s] = E;
}

// ---------------------------------------------------------------------------
// GEMM kernels (identical to the proven R6 configuration)
// ---------------------------------------------------------------------------
// pre: Pb = bf16(A@W + bias)   (A fp32)
__global__ void __launch_bounds__(256, 3)
gemm_pre(const float* __restrict__ A, const __nv_bfloat16* __restrict__ Wt,
         const float* __restrict__ bias, __nv_bfloat16* __restrict__ Pb, int M)
{
    extern __shared__ char smem[];
    uint32_t sA = smem_u32(smem), sB = sA + SMEM_A;
    int tid = threadIdx.x, lane = tid & 31, wid = tid >> 5;
    int wm = wid & 1, wn = wid >> 1, g = lane >> 2, tg = lane & 3;
    int tile0 = blockIdx.x * 64;

    fill_A(smem, A, tile0, M, tid);
    fill_B(smem + SMEM_A, Wt, tid);
    __syncthreads();

    float acc[2][4][4];
#pragma unroll
    for (int mt = 0; mt < 2; mt++)
#pragma unroll
        for (int nt = 0; nt < 4; nt++)
#pragma unroll
            for (int j = 0; j < 4; j++) acc[mt][nt][j] = 0.f;
    mma_tile(sA, sB, acc, lane, wm, wn);

#pragma unroll
    for (int mt = 0; mt < 2; mt++) {
        int r0 = tile0 + wm * 32 + mt * 16 + g;
#pragma unroll
        for (int nt = 0; nt < 4; nt++) {
            int c0 = wn * 32 + nt * 8 + tg * 2;
            float b0 = __ldg(bias + c0), b1 = __ldg(bias + c0 + 1);
            if (r0 < M) {
                __nv_bfloat162 o = __floats2bfloat162_rn(acc[mt][nt][0] + b0,
                                                         acc[mt][nt][1] + b1);
                *reinterpret_cast<uint32_t*>(Pb + (size_t)r0 * 128 + c0) =
                    *reinterpret_cast<uint32_t*>(&o);
            }
            if (r0 + 8 < M) {
                __nv_bfloat162 o = __floats2bfloat162_rn(acc[mt][nt][2] + b0,
                                                         acc[mt][nt][3] + b1);
                *reinterpret_cast<uint32_t*>(Pb + (size_t)(r0 + 8) * 128 + c0) =
                    *reinterpret_cast<uint32_t*>(&o);
            }
        }
    }
}

// mid: x1 = interp + poolb@W1 + bo0 (fp32 out); then Pb = bf16(x1@W2 + bb1)
__global__ void __launch_bounds__(256, 2)
gemm_mid(const __nv_bfloat16* __restrict__ poolb,
         const __nv_bfloat16* __restrict__ Wt1,
         const float* __restrict__ bo0, const float* __restrict__ interp,
         float* __restrict__ x1, const __nv_bfloat16* __restrict__ Wt2,
         const float* __restrict__ bb1, __nv_bfloat16* __restrict__ Pb, int M)
{
    extern __shared__ char smem[];
    uint32_t sA = smem_u32(smem), sB1 = sA + SMEM_A, sB2 = sB1 + SMEM_B;
    int tid = threadIdx.x, lane = tid & 31, wid = tid >> 5;
    int wm = wid & 1, wn = wid >> 1, g = lane >> 2, tg = lane & 3;
    int tile0 = blockIdx.x * 64;

    fill_Abf(smem, poolb, tile0, M, tid);
    fill_B(smem + SMEM_A, Wt1, tid);
    fill_B(smem + SMEM_A + SMEM_B, Wt2, tid);
    __syncthreads();

    float acc[2][4][4];
#pragma unroll
    for (int mt = 0; mt < 2; mt++)
#pragma unroll
        for (int nt = 0; nt < 4; nt++)
#pragma unroll
            for (int j = 0; j < 4; j++) acc[mt][nt][j] = 0.f;
    mma_tile(sA, sB1, acc, lane, wm, wn);
    __syncthreads();                        // all reads of A done before overwrite

    // Phase-A epilogue: x1 = resid + acc + bias; fp32 -> gmem, bf16 -> A smem
#pragma unroll
    for (int mt = 0; mt < 2; mt++) {
        int rl = wm * 32 + mt * 16 + g;
        int r0 = tile0 + rl;
#pragma unroll
        for (int nt = 0; nt < 4; nt++) {
            int c0 = wn * 32 + nt * 8 + tg * 2;
            float b0 = __ldg(bo0 + c0), b1 = __ldg(bo0 + c0 + 1);
            if (r0 < M) {
                float2 rv = *reinterpret_cast<const float2*>(
                    interp + (size_t)r0 * 128 + c0);
                float v0 = acc[mt][nt][0] + b0 + rv.x;
                float v1 = acc[mt][nt][1] + b1 + rv.y;
                *reinterpret_cast<float2*>(x1 + (size_t)r0 * 128 + c0) =
                    make_float2(v0, v1);
                __nv_bfloat162 o = __floats2bfloat162_rn(v0, v1);
                *reinterpret_cast<uint32_t*>(smem + rl * (BSTR * 2) + c0 * 2) =
                    *reinterpret_cast<uint32_t*>(&o);
            }
            if (r0 + 8 < M) {
                float2 rv = *reinterpret_cast<const float2*>(
                    interp + (size_t)(r0 + 8) * 128 + c0);
                float v0 = acc[mt][nt][2] + b0 + rv.x;
                float v1 = acc[mt][nt][3] + b1 + rv.y;
                *reinterpret_cast<float2*>(x1 + (size_t)(r0 + 8) * 128 + c0) =
                    make_float2(v0, v1);
                __nv_bfloat162 o = __floats2bfloat162_rn(v0, v1);
                *reinterpret_cast<uint32_t*>(smem + (rl + 8) * (BSTR * 2) + c0 * 2) =
                    *reinterpret_cast<uint32_t*>(&o);
            }
        }
    }
    __syncthreads();

    // Phase B: Pb = bf16(x1@W2 + bb1)
#pragma unroll
    for (int mt = 0; mt < 2; mt++)
#pragma unroll
        for (int nt = 0; nt < 4; nt++)
#pragma unroll
            for (int j = 0; j < 4; j++) acc[mt][nt][j] = 0.f;
    mma_tile(sA, sB2, acc, lane, wm, wn);

#pragma unroll
    for (int mt = 0; mt < 2; mt++) {
        int r0 = tile0 + wm * 32 + mt * 16 + g;
#pragma unroll
        for (int nt = 0; nt < 4; nt++) {
            int c0 = wn * 32 + nt * 8 + tg * 2;
            float b0 = __ldg(bb1 + c0), b1 = __ldg(bb1 + c0 + 1);
            if (r0 < M) {
                __nv_bfloat162 o = __floats2bfloat162_rn(acc[mt][nt][0] + b0,
                                                         acc[mt][nt][1] + b1);
                *reinterpret_cast<uint32_t*>(Pb + (size_t)r0 * 128 + c0) =
                    *reinterpret_cast<uint32_t*>(&o);
            }
            if (r0 + 8 < M) {
                __nv_bfloat162 o = __floats2bfloat162_rn(acc[mt][nt][2] + b0,
                                                         acc[mt][nt][3] + b1);
                *reinterpret_cast<uint32_t*>(Pb + (size_t)(r0 + 8) * 128 + c0) =
                    *reinterpret_cast<uint32_t*>(&o);
            }
        }
    }
}

// fin: out = (x1 + poolb@W3 + bo1) @ Wf + bf
__global__ void __launch_bounds__(256, 3)
gemm_fin(const __nv_bfloat16* __restrict__ poolb,
         const __nv_bfloat16* __restrict__ Wt3,
         const float* __restrict__ bo1, const float* __restrict__ x1,
         const float* __restrict__ Wf, const float* __restrict__ bfp,
         float* __restrict__ out, int M)
{
    extern __shared__ char smem[];
    uint32_t sA = smem_u32(smem), sB = sA + SMEM_A;
    int tid = threadIdx.x, lane = tid & 31, wid = tid >> 5;
    int wm = wid & 1, wn = wid >> 1, g = lane >> 2, tg = lane & 3;
    int tile0 = blockIdx.x * 64;

    fill_Abf(smem, poolb, tile0, M, tid);
    fill_B(smem + SMEM_A, Wt3, tid);
    __syncthreads();

    float acc[2][4][4];
#pragma unroll
    for (int mt = 0; mt < 2; mt++)
#pragma unroll
        for (int nt = 0; nt < 4; nt++)
#pragma unroll
            for (int j = 0; j < 4; j++) acc[mt][nt][j] = 0.f;
    mma_tile(sA, sB, acc, lane, wm, wn);
    __syncthreads();                        // done with A/B smem -> reuse for hp

    float* hp = reinterpret_cast<float*>(smem);   // [64][17]
#pragma unroll
    for (int mt = 0; mt < 2; mt++) {
        int rl = wm * 32 + mt * 16 + g;
        int r0 = tile0 + rl;
        float plo = 0.f, phi = 0.f;
#pragma unroll
        for (int nt = 0; nt < 4; nt++) {
            int c0 = wn * 32 + nt * 8 + tg * 2;
            float b0 = __ldg(bo1 + c0), b1 = __ldg(bo1 + c0 + 1);
            float w0 = __ldg(Wf + c0),  w1 = __ldg(Wf + c0 + 1);
            float v0 = acc[mt][nt][0] + b0, v1 = acc[mt][nt][1] + b1;
            float u0 = acc[mt][nt][2] + b0, u1 = acc[mt][nt][3] + b1;
            if (r0 < M) {
                float2 rv = *reinterpret_cast<const float2*>(
                    x1 + (size_t)r0 * 128 + c0);
                plo += (v0 + rv.x) * w0 + (v1 + rv.y) * w1;
            }
            if (r0 + 8 < M) {
                float2 rv = *reinterpret_cast<const float2*>(
                    x1 + (size_t)(r0 + 8) * 128 + c0);
                phi += (u0 + rv.x) * w0 + (u1 + rv.y) * w1;
            }
        }
        hp[rl * 17 + wn * 4 + tg] = plo;
        hp[(rl + 8) * 17 + wn * 4 + tg] = phi;
    }
    __syncthreads();
    if (tid < 64) {
        int r0 = tile0 + tid;
        if (r0 < M) {
            float s = 0.f;
#pragma unroll
            for (int j = 0; j < 16; j++) s += hp[tid * 17 + j];
            out[r0] = s + __ldg(bfp);
        }
    }
}

// ---------------------------------------------------------------------------
// Edge kernel (CSR, warp per segment, smem meta staging): per 8 edges, lanes
// 0-7 do ONE coalesced 128B meta LDG -> STS; per-edge meta becomes a 29-cyc
// LDS broadcast. Edges processed in pairs with back-to-back P gathers
// (MLP=2). h = P[idx] + add@Wadd (HFMA2); running max (HMAX2, zero-init =
// relu fold); plain uint2 store. No atomics, no zeroing. Thread owns 4 cols.
// Meta reads past the segment stay within g_edge (EMAX > E) and are never
// consumed.
// ---------------------------------------------------------------------------
#define EDGE_PROC(md, pv) do {                                               \
    __nv_bfloat162 axy = *reinterpret_cast<__nv_bfloat162*>(&(md).y);        \
    __nv_bfloat162 azw = *reinterpret_cast<__nv_bfloat162*>(&(md).z);        \
    __nv_bfloat162 ax = __low2bfloat162(axy),  ay = __high2bfloat162(axy);   \
    __nv_bfloat162 az = __low2bfloat162(azw),  aw = __high2bfloat162(azw);   \
    __nv_bfloat162 h0 = *reinterpret_cast<__nv_bfloat162*>(&(pv).x);         \
    __nv_bfloat162 h1 = *reinterpret_cast<__nv_bfloat162*>(&(pv).y);         \
    h0 = __hfma2(ax, wa2[0][0], h0); h1 = __hfma2(ax, wa2[0][1], h1);        \
    h0 = __hfma2(ay, wa2[1][0], h0); h1 = __hfma2(ay, wa2[1][1], h1);        \
    h0 = __hfma2(az, wa2[2][0], h0); h1 = __hfma2(az, wa2[2][1], h1);        \
    h0 = __hfma2(aw, wa2[3][0], h0); h1 = __hfma2(aw, wa2[3][1], h1);        \
    m0 = __hmax2(m0, h0); m1 = __hmax2(m1, h1);                              \
} while (0)

__global__ void __launch_bounds__(256)
edge_kernel(const uint2* __restrict__ Pr, const uint4* __restrict__ em,
            const int* __restrict__ start, const float* __restrict__ Wadd,
            uint2* __restrict__ poolb, int N)
{
    __shared__ uint4 smeta[8][8];           // [warp][slot], 1 KB
    int w = threadIdx.x >> 5, lane = threadIdx.x & 31;
    int s = blockIdx.x * 8 + w;
    if (s >= N) return;
    int e  = __ldg(start + s);
    int en = __ldg(start + s + 1);

    int cb = lane * 4;
    __nv_bfloat162 wa2[4][2];
#pragma unroll
    for (int a = 0; a < 4; a++)
#pragma unroll
        for (int p = 0; p < 2; p++)
            wa2[a][p] = __floats2bfloat162_rn(__ldg(Wadd + a * 128 + cb + 2 * p),
                                              __ldg(Wadd + a * 128 + cb + 2 * p + 1));

    __nv_bfloat162 z2 = __floats2bfloat162_rn(0.f, 0.f);
    __nv_bfloat162 m0 = z2, m1 = z2;

    while (e < en) {
        // Stage 8 metas: one coalesced 128B load by lanes 0-7.
        if (lane < 8) smeta[w][lane] = __ldg(em + e + lane);
        __syncwarp();
        int cnt = en - e;
        if (cnt >= 8) {
#pragma unroll
            for (int j = 0; j < 8; j += 2) {
                uint4 mdA = smeta[w][j];
                uint4 mdB = smeta[w][j + 1];
                uint2 pvA = __ldg(Pr + (size_t)mdA.x * 32 + lane);
                uint2 pvB = __ldg(Pr + (size_t)mdB.x * 32 + lane);
                EDGE_PROC(mdA, pvA);
                EDGE_PROC(mdB, pvB);
            }
        } else {
            for (int j = 0; j < cnt; j++) {
                uint4 md = smeta[w][j];
                uint2 pv = __ldg(Pr + (size_t)md.x * 32 + lane);
                EDGE_PROC(md, pv);
            }
        }
        e += 8;
        __syncwarp();
    }

    uint2 o;
    o.x = *reinterpret_cast<uint32_t*>(&m0);
    o.y = *reinterpret_cast<uint32_t*>(&m1);
    poolb[(size_t)s * 32 + lane] = o;
}

// ---------------------------------------------------------------------------
extern "C" void kernel_launch(void* const* d_in, const int* in_sizes, int n_in,
                              void* d_out, int out_size)
{
    const float* interp = (const float*)d_in[0];
    const float* add    = (const float*)d_in[1];
    const int*   nidx   = (const int*)d_in[2];
    const int*   segs   = (const int*)d_in[3];
    const float* Wb0 = (const float*)d_in[4];
    const float* bb0 = (const float*)d_in[5];
    const float* Wo0 = (const float*)d_in[6];
    const float* bo0 = (const float*)d_in[7];
    const float* Wb1 = (const float*)d_in[8];
    const float* bb1 = (const float*)d_in[9];
    const float* Wo1 = (const float*)d_in[10];
    const float* bo1 = (const float*)d_in[11];
    const float* Wf  = (const float*)d_in[12];
    const float* bf  = (const float*)d_in[13];
    float* out = (float*)d_out;

    int N = in_sizes[0] / 128;
    int E = in_sizes[2];

    __nv_bfloat16 *P, *poolb, *Wt;
    float *x1;
    uint4* em;
    int* start;
    cudaGetSymbolAddress((void**)&P, g_P);
    cudaGetSymbolAddress((void**)&poolb, g_poolb);
    cudaGetSymbolAddress((void**)&x1, g_x1);
    cudaGetSymbolAddress((void**)&Wt, g_Wt);
    cudaGetSymbolAddress((void**)&em, g_edge);
    cudaGetSymbolAddress((void**)&start, g_start);

    cudaFuncSetAttribute(gemm_pre, cudaFuncAttributeMaxDynamicSharedMemorySize, SMEM_PF);
    cudaFuncSetAttribute(gemm_mid, cudaFuncAttributeMaxDynamicSharedMemorySize, SMEM_MID);
    cudaFuncSetAttribute(gemm_fin, cudaFuncAttributeMaxDynamicSharedMemorySize, SMEM_PF);

    int gtiles = (N + 63) / 64;
    int sgrid = (N + 7) / 8;

    prep_w<<<dim3(64, 4), 256>>>(Wb0, Wo0, Wb1, Wo1, Wt);
    prep_edge<<<(E + 255) / 256, 256>>>(segs, nidx, (const float4*)add, em,
                                        start, E, N);

    // Block 0
    gemm_pre<<<gtiles, 256, SMEM_PF>>>(interp, Wt + 0 * 16384, bb0, P, N);
    edge_kernel<<<sgrid, 256>>>((const uint2*)P, em, start, Wb0 + 128 * 128,
                                (uint2*)poolb, N);
    // Block-0 projection + Block-1 pre-edge GEMM fused
    gemm_mid<<<gtiles, 256, SMEM_MID>>>(poolb, Wt + 1 * 16384, bo0, interp, x1,
                                        Wt + 2 * 16384, bb1, P, N);
    edge_kernel<<<sgrid, 256>>>((const uint2*)P, em, start, Wb1 + 128 * 128,
                                (uint2*)poolb, N);
    // Block-1 projection + final head fused
    gemm_fin<<<gtiles, 256, SMEM_PF>>>(poolb, Wt + 3 * 16384, bo1, x1, Wf, bf,
                                       out, N);
}

// round 16
// speedup vs baseline: 1.9799x; 1.0556x over previous
#include <cuda_runtime.h>
#include <cuda_bf16.h>
#include <cstdint>

// ---------------------------------------------------------------------------
// Problem shape (fixed by dataset): N=50000, E=1.6M, D=128, A=4, H=128
// ---------------------------------------------------------------------------
#define NMAX 50048          // 782 tiles of 64
#define EMAX 1700000
#define DDIM 128

__device__ __nv_bfloat16 g_P[(size_t)NMAX * DDIM];      // bf16 activations (pre-edge)
__device__ __nv_bfloat16 g_poolb[(size_t)NMAX * DDIM];  // bf16 pooled output
__device__ float g_x1  [(size_t)NMAX * DDIM];           // fp32 residual stream
__device__ __nv_bfloat16 g_Wt[4 * 128 * 128];           // transposed bf16 weights
__device__ uint4 g_edge[EMAX];                          // packed {idx, bf16 add x4, 0}
__device__ int   g_start[NMAX + 1];                     // CSR segment starts

// ---------------------------------------------------------------------------
// helpers
// ---------------------------------------------------------------------------
__device__ __forceinline__ uint32_t smem_u32(const void* p) {
    uint32_t a;
    asm("{ .reg .u64 t; cvta.to.shared.u64 t, %1; cvt.u32.u64 %0, t; }"
        : "=r"(a) : "l"(p));
    return a;
}
__device__ __forceinline__ void ldsm_x4(uint32_t& r0, uint32_t& r1,
                                        uint32_t& r2, uint32_t& r3, uint32_t a) {
    asm volatile("ldmatrix.sync.aligned.m8n8.x4.shared.b16 {%0,%1,%2,%3}, [%4];"
                 : "=r"(r0), "=r"(r1), "=r"(r2), "=r"(r3) : "r"(a));
}
__device__ __forceinline__ void ldsm_x2(uint32_t& r0, uint32_t& r1, uint32_t a) {
    asm volatile("ldmatrix.sync.aligned.m8n8.x2.shared.b16 {%0,%1}, [%2];"
                 : "=r"(r0), "=r"(r1) : "r"(a));
}
__device__ __forceinline__ void mma_bf16(float* c, const uint32_t* a, const uint32_t* b) {
    asm volatile(
        "mma.sync.aligned.m16n8k16.row.col.f32.bf16.bf16.f32 "
        "{%0,%1,%2,%3}, {%4,%5,%6,%7}, {%8,%9}, {%0,%1,%2,%3};"
        : "+f"(c[0]), "+f"(c[1]), "+f"(c[2]), "+f"(c[3])
        : "r"(a[0]), "r"(a[1]), "r"(a[2]), "r"(a[3]), "r"(b[0]), "r"(b[1]));
}

// ---------------------------------------------------------------------------
// Tiling constants: CTA = 64 rows x 128 cols, 8 warps (2 m x 4 n), K=128
// ---------------------------------------------------------------------------
#define BSTR 136                              // bf16 elems per smem row (pad 8)
static constexpr int SMEM_A  = 64 * BSTR * 2;    // 17408
static constexpr int SMEM_B  = 128 * BSTR * 2;   // 34816
static constexpr int SMEM_PF = SMEM_A + SMEM_B;          // 52224 (pre/fin)
static constexpr int SMEM_MID = SMEM_A + 2 * SMEM_B;     // 87040 (mid)

// A tile fill: 64x128 fp32 -> bf16 smem
__device__ __forceinline__ void fill_A(char* smem, const float* __restrict__ A,
                                       int tile0, int M, int tid) {
#pragma unroll
    for (int it = 0; it < 8; it++) {
        int p = it * 256 + tid;               // 0..2047
        int r = p >> 5, c = p & 31;
        int gr = tile0 + r;
        float4 v = make_float4(0.f, 0.f, 0.f, 0.f);
        if (gr < M) v = __ldg(reinterpret_cast<const float4*>(A + (size_t)gr * 128) + c);
        __nv_bfloat162 lo = __floats2bfloat162_rn(v.x, v.y);
        __nv_bfloat162 hi = __floats2bfloat162_rn(v.z, v.w);
        uint2 o = make_uint2(*reinterpret_cast<uint32_t*>(&lo),
                             *reinterpret_cast<uint32_t*>(&hi));
        *reinterpret_cast<uint2*>(smem + r * (BSTR * 2) + c * 8) = o;
    }
}
// A tile fill from bf16 source (straight copy)
__device__ __forceinline__ void fill_Abf(char* smem, const __nv_bfloat16* __restrict__ A,
                                         int tile0, int M, int tid) {
    const uint4* src = reinterpret_cast<const uint4*>(A + (size_t)tile0 * 128);
#pragma unroll
    for (int it = 0; it < 4; it++) {
        int p = it * 256 + tid;               // 0..1023
        int r = p >> 4, c = p & 15;
        uint4 v = make_uint4(0, 0, 0, 0);
        if (tile0 + r < M) v = __ldg(src + p);
        *reinterpret_cast<uint4*>(smem + r * (BSTR * 2) + c * 16) = v;
    }
}
// B tile fill: 128x128 bf16 (pre-transposed) -> smem, uint4 copies
__device__ __forceinline__ void fill_B(char* dst, const __nv_bfloat16* __restrict__ Wt,
                                       int tid) {
    const uint4* src = reinterpret_cast<const uint4*>(Wt);
#pragma unroll
    for (int it = 0; it < 8; it++) {
        int p = it * 256 + tid;               // 0..2047
        int n = p >> 4, c = p & 15;
        *reinterpret_cast<uint4*>(dst + n * (BSTR * 2) + c * 16) = src[p];
    }
}
// MMA core: acc[2][4][4] over 64x128 tile
__device__ __forceinline__ void mma_tile(uint32_t sA, uint32_t sB,
                                         float acc[2][4][4], int lane,
                                         int wm, int wn) {
    int aRow = wm * 32 + (lane & 15);
    int aCol = (lane >> 4) * 8;
    int bRow = wn * 32 + (lane & 7);
    int bCol = ((lane >> 3) & 1) * 8;
#pragma unroll
    for (int k = 0; k < 8; k++) {
        uint32_t a[2][4], b[4][2];
#pragma unroll
        for (int mt = 0; mt < 2; mt++)
            ldsm_x4(a[mt][0], a[mt][1], a[mt][2], a[mt][3],
                    sA + (aRow + mt * 16) * (BSTR * 2) + (k * 16 + aCol) * 2);
#pragma unroll
        for (int nt = 0; nt < 4; nt++)
            ldsm_x2(b[nt][0], b[nt][1],
                    sB + (bRow + nt * 8) * (BSTR * 2) + (k * 16 + bCol) * 2);
#pragma unroll
        for (int mt = 0; mt < 2; mt++)
#pragma unroll
            for (int nt = 0; nt < 4; nt++)
                mma_bf16(acc[mt][nt], a[mt], b[nt]);
    }
}

// ---------------------------------------------------------------------------
// prep: Wt[w][n][k] = bf16(W_w[k][n])
// ---------------------------------------------------------------------------
__global__ void __launch_bounds__(256)
prep_w(const float* __restrict__ W0, const float* __restrict__ W1,
       const float* __restrict__ W2, const float* __restrict__ W3,
       __nv_bfloat16* __restrict__ Wt)
{
    const float* Ws[4] = {W0, W1, W2, W3};
    const float* W = Ws[blockIdx.y];
    __nv_bfloat16* dst = Wt + (size_t)blockIdx.y * 16384;
    int i = blockIdx.x * 256 + threadIdx.x;
    int n = i >> 7, k = i & 127;
    dst[n * 128 + k] = __float2bfloat16(W[k * 128 + n]);
}

// prep: pack per-edge meta {idx, bf16(add.xy), bf16(add.zw), 0} + CSR starts
__global__ void __launch_bounds__(256)
prep_edge(const int* __restrict__ segs, const int* __restrict__ nidx,
          const float4* __restrict__ add, uint4* __restrict__ em,
          int* __restrict__ start, int E, int N)
{
    int i = blockIdx.x * 256 + threadIdx.x;
    if (i >= E) return;
    float4 ad = __ldg(add + i);
    __nv_bfloat162 lo = __floats2bfloat162_rn(ad.x, ad.y);
    __nv_bfloat162 hi = __floats2bfloat162_rn(ad.z, ad.w);
    em[i] = make_uint4((uint32_t)__ldg(nidx + i),
                       *reinterpret_cast<uint32_t*>(&lo),
                       *reinterpret_cast<uint32_t*>(&hi), 0u);
    int b = __ldg(segs + i);
    int a = (i == 0) ? -1 : __ldg(segs + i - 1);
    for (int s = a + 1; s <= b; s++) start[s] = i;
    if (i == E - 1)
        for (int s = b + 1; s <= N; s++) start[s] = E;
}

// ---------------------------------------------------------------------------
// GEMM kernels (identical to the proven R6 configuration)
// ---------------------------------------------------------------------------
// pre: Pb = bf16(A@W + bias)   (A fp32)
__global__ void __launch_bounds__(256, 3)
gemm_pre(const float* __restrict__ A, const __nv_bfloat16* __restrict__ Wt,
         const float* __restrict__ bias, __nv_bfloat16* __restrict__ Pb, int M)
{
    extern __shared__ char smem[];
    uint32_t sA = smem_u32(smem), sB = sA + SMEM_A;
    int tid = threadIdx.x, lane = tid & 31, wid = tid >> 5;
    int wm = wid & 1, wn = wid >> 1, g = lane >> 2, tg = lane & 3;
    int tile0 = blockIdx.x * 64;

    fill_A(smem, A, tile0, M, tid);
    fill_B(smem + SMEM_A, Wt, tid);
    __syncthreads();

    float acc[2][4][4];
#pragma unroll
    for (int mt = 0; mt < 2; mt++)
#pragma unroll
        for (int nt = 0; nt < 4; nt++)
#pragma unroll
            for (int j = 0; j < 4; j++) acc[mt][nt][j] = 0.f;
    mma_tile(sA, sB, acc, lane, wm, wn);

#pragma unroll
    for (int mt = 0; mt < 2; mt++) {
        int r0 = tile0 + wm * 32 + mt * 16 + g;
#pragma unroll
        for (int nt = 0; nt < 4; nt++) {
            int c0 = wn * 32 + nt * 8 + tg * 2;
            float b0 = __ldg(bias + c0), b1 = __ldg(bias + c0 + 1);
            if (r0 < M) {
                __nv_bfloat162 o = __floats2bfloat162_rn(acc[mt][nt][0] + b0,
                                                         acc[mt][nt][1] + b1);
                *reinterpret_cast<uint32_t*>(Pb + (size_t)r0 * 128 + c0) =
                    *reinterpret_cast<uint32_t*>(&o);
            }
            if (r0 + 8 < M) {
                __nv_bfloat162 o = __floats2bfloat162_rn(acc[mt][nt][2] + b0,
                                                         acc[mt][nt][3] + b1);
                *reinterpret_cast<uint32_t*>(Pb + (size_t)(r0 + 8) * 128 + c0) =
                    *reinterpret_cast<uint32_t*>(&o);
            }
        }
    }
}

// mid: x1 = interp + poolb@W1 + bo0 (fp32 out); then Pb = bf16(x1@W2 + bb1)
__global__ void __launch_bounds__(256, 2)
gemm_mid(const __nv_bfloat16* __restrict__ poolb,
         const __nv_bfloat16* __restrict__ Wt1,
         const float* __restrict__ bo0, const float* __restrict__ interp,
         float* __restrict__ x1, const __nv_bfloat16* __restrict__ Wt2,
         const float* __restrict__ bb1, __nv_bfloat16* __restrict__ Pb, int M)
{
    extern __shared__ char smem[];
    uint32_t sA = smem_u32(smem), sB1 = sA + SMEM_A, sB2 = sB1 + SMEM_B;
    int tid = threadIdx.x, lane = tid & 31, wid = tid >> 5;
    int wm = wid & 1, wn = wid >> 1, g = lane >> 2, tg = lane & 3;
    int tile0 = blockIdx.x * 64;

    fill_Abf(smem, poolb, tile0, M, tid);
    fill_B(smem + SMEM_A, Wt1, tid);
    fill_B(smem + SMEM_A + SMEM_B, Wt2, tid);
    __syncthreads();

    float acc[2][4][4];
#pragma unroll
    for (int mt = 0; mt < 2; mt++)
#pragma unroll
        for (int nt = 0; nt < 4; nt++)
#pragma unroll
            for (int j = 0; j < 4; j++) acc[mt][nt][j] = 0.f;
    mma_tile(sA, sB1, acc, lane, wm, wn);
    __syncthreads();                        // all reads of A done before overwrite

    // Phase-A epilogue: x1 = resid + acc + bias; fp32 -> gmem, bf16 -> A smem
#pragma unroll
    for (int mt = 0; mt < 2; mt++) {
        int rl = wm * 32 + mt * 16 + g;
        int r0 = tile0 + rl;
#pragma unroll
        for (int nt = 0; nt < 4; nt++) {
            int c0 = wn * 32 + nt * 8 + tg * 2;
            float b0 = __ldg(bo0 + c0), b1 = __ldg(bo0 + c0 + 1);
            if (r0 < M) {
                float2 rv = *reinterpret_cast<const float2*>(
                    interp + (size_t)r0 * 128 + c0);
                float v0 = acc[mt][nt][0] + b0 + rv.x;
                float v1 = acc[mt][nt][1] + b1 + rv.y;
                *reinterpret_cast<float2*>(x1 + (size_t)r0 * 128 + c0) =
                    make_float2(v0, v1);
                __nv_bfloat162 o = __floats2bfloat162_rn(v0, v1);
                *reinterpret_cast<uint32_t*>(smem + rl * (BSTR * 2) + c0 * 2) =
                    *reinterpret_cast<uint32_t*>(&o);
            }
            if (r0 + 8 < M) {
                float2 rv = *reinterpret_cast<const float2*>(
                    interp + (size_t)(r0 + 8) * 128 + c0);
                float v0 = acc[mt][nt][2] + b0 + rv.x;
                float v1 = acc[mt][nt][3] + b1 + rv.y;
                *reinterpret_cast<float2*>(x1 + (size_t)(r0 + 8) * 128 + c0) =
                    make_float2(v0, v1);
                __nv_bfloat162 o = __floats2bfloat162_rn(v0, v1);
                *reinterpret_cast<uint32_t*>(smem + (rl + 8) * (BSTR * 2) + c0 * 2) =
                    *reinterpret_cast<uint32_t*>(&o);
            }
        }
    }
    __syncthreads();

    // Phase B: Pb = bf16(x1@W2 + bb1)
#pragma unroll
    for (int mt = 0; mt < 2; mt++)
#pragma unroll
        for (int nt = 0; nt < 4; nt++)
#pragma unroll
            for (int j = 0; j < 4; j++) acc[mt][nt][j] = 0.f;
    mma_tile(sA, sB2, acc, lane, wm, wn);

#pragma unroll
    for (int mt = 0; mt < 2; mt++) {
        int r0 = tile0 + wm * 32 + mt * 16 + g;
#pragma unroll
        for (int nt = 0; nt < 4; nt++) {
            int c0 = wn * 32 + nt * 8 + tg * 2;
            float b0 = __ldg(bb1 + c0), b1 = __ldg(bb1 + c0 + 1);
            if (r0 < M) {
                __nv_bfloat162 o = __floats2bfloat162_rn(acc[mt][nt][0] + b0,
                                                         acc[mt][nt][1] + b1);
                *reinterpret_cast<uint32_t*>(Pb + (size_t)r0 * 128 + c0) =
                    *reinterpret_cast<uint32_t*>(&o);
            }
            if (r0 + 8 < M) {
                __nv_bfloat162 o = __floats2bfloat162_rn(acc[mt][nt][2] + b0,
                                                         acc[mt][nt][3] + b1);
                *reinterpret_cast<uint32_t*>(Pb + (size_t)(r0 + 8) * 128 + c0) =
                    *reinterpret_cast<uint32_t*>(&o);
            }
        }
    }
}

// fin: out = (x1 + poolb@W3 + bo1) @ Wf + bf
__global__ void __launch_bounds__(256, 3)
gemm_fin(const __nv_bfloat16* __restrict__ poolb,
         const __nv_bfloat16* __restrict__ Wt3,
         const float* __restrict__ bo1, const float* __restrict__ x1,
         const float* __restrict__ Wf, const float* __restrict__ bfp,
         float* __restrict__ out, int M)
{
    extern __shared__ char smem[];
    uint32_t sA = smem_u32(smem), sB = sA + SMEM_A;
    int tid = threadIdx.x, lane = tid & 31, wid = tid >> 5;
    int wm = wid & 1, wn = wid >> 1, g = lane >> 2, tg = lane & 3;
    int tile0 = blockIdx.x * 64;

    fill_Abf(smem, poolb, tile0, M, tid);
    fill_B(smem + SMEM_A, Wt3, tid);
    __syncthreads();

    float acc[2][4][4];
#pragma unroll
    for (int mt = 0; mt < 2; mt++)
#pragma unroll
        for (int nt = 0; nt < 4; nt++)
#pragma unroll
            for (int j = 0; j < 4; j++) acc[mt][nt][j] = 0.f;
    mma_tile(sA, sB, acc, lane, wm, wn);
    __syncthreads();                        // done with A/B smem -> reuse for hp

    float* hp = reinterpret_cast<float*>(smem);   // [64][17]
#pragma unroll
    for (int mt = 0; mt < 2; mt++) {
        int rl = wm * 32 + mt * 16 + g;
        int r0 = tile0 + rl;
        float plo = 0.f, phi = 0.f;
#pragma unroll
        for (int nt = 0; nt < 4; nt++) {
            int c0 = wn * 32 + nt * 8 + tg * 2;
            float b0 = __ldg(bo1 + c0), b1 = __ldg(bo1 + c0 + 1);
            float w0 = __ldg(Wf + c0),  w1 = __ldg(Wf + c0 + 1);
            float v0 = acc[mt][nt][0] + b0, v1 = acc[mt][nt][1] + b1;
            float u0 = acc[mt][nt][2] + b0, u1 = acc[mt][nt][3] + b1;
            if (r0 < M) {
                float2 rv = *reinterpret_cast<const float2*>(
                    x1 + (size_t)r0 * 128 + c0);
                plo += (v0 + rv.x) * w0 + (v1 + rv.y) * w1;
            }
            if (r0 + 8 < M) {
                float2 rv = *reinterpret_cast<const float2*>(
                    x1 + (size_t)(r0 + 8) * 128 + c0);
                phi += (u0 + rv.x) * w0 + (u1 + rv.y) * w1;
            }
        }
        hp[rl * 17 + wn * 4 + tg] = plo;
        hp[(rl + 8) * 17 + wn * 4 + tg] = phi;
    }
    __syncthreads();
    if (tid < 64) {
        int r0 = tile0 + tid;
        if (r0 < M) {
            float s = 0.f;
#pragma unroll
            for (int j = 0; j < 16; j++) s += hp[tid * 17 + j];
            out[r0] = s + __ldg(bfp);
        }
    }
}

// ---------------------------------------------------------------------------
// Edge kernel (CSR, warp per segment): R6 loop body verbatim; only the
// unroll factor (4) and launch bounds (256, 6 -> 42-reg budget) changed, to
// let ptxas batch independent meta loads across unrolled iterations
// (MLP_eff from register allocation, per B300 microarch doc). h = P[idx] +
// add@Wadd (HFMA2); running max (HMAX2, zero-init = relu fold); plain uint2
// store. No atomics, no zeroing. Thread owns 4 columns.
// ---------------------------------------------------------------------------
#define EDGE_PROC(md, pv) do {                                               \
    __nv_bfloat162 axy = *reinterpret_cast<__nv_bfloat162*>(&(md).y);        \
    __nv_bfloat162 azw = *reinterpret_cast<__nv_bfloat162*>(&(md).z);        \
    __nv_bfloat162 ax = __low2bfloat162(axy),  ay = __high2bfloat162(axy);   \
    __nv_bfloat162 az = __low2bfloat162(azw),  aw = __high2bfloat162(azw);   \
    __nv_bfloat162 h0 = *reinterpret_cast<__nv_bfloat162*>(&(pv).x);         \
    __nv_bfloat162 h1 = *reinterpret_cast<__nv_bfloat162*>(&(pv).y);         \
    h0 = __hfma2(ax, wa2[0][0], h0); h1 = __hfma2(ax, wa2[0][1], h1);        \
    h0 = __hfma2(ay, wa2[1][0], h0); h1 = __hfma2(ay, wa2[1][1], h1);        \
    h0 = __hfma2(az, wa2[2][0], h0); h1 = __hfma2(az, wa2[2][1], h1);        \
    h0 = __hfma2(aw, wa2[3][0], h0); h1 = __hfma2(aw, wa2[3][1], h1);        \
    m0 = __hmax2(m0, h0); m1 = __hmax2(m1, h1);                              \
} while (0)

__global__ void __launch_bounds__(256, 6)
edge_kernel(const uint2* __restrict__ Pr, const uint4* __restrict__ em,
            const int* __restrict__ start, const float* __restrict__ Wadd,
            uint2* __restrict__ poolb, int N)
{
    int s = blockIdx.x * 8 + (threadIdx.x >> 5);
    if (s >= N) return;
    int lane = threadIdx.x & 31;
    int e  = __ldg(start + s);
    int en = __ldg(start + s + 1);

    int cb = lane * 4;
    __nv_bfloat162 wa2[4][2];
#pragma unroll
    for (int a = 0; a < 4; a++)
#pragma unroll
        for (int p = 0; p < 2; p++)
            wa2[a][p] = __floats2bfloat162_rn(__ldg(Wadd + a * 128 + cb + 2 * p),
                                              __ldg(Wadd + a * 128 + cb + 2 * p + 1));

    __nv_bfloat162 z2 = __floats2bfloat162_rn(0.f, 0.f);
    __nv_bfloat162 m0 = z2, m1 = z2;

#pragma unroll 4
    for (; e < en; ++e) {
        uint4 md = __ldg(em + e);
        uint2 pv = __ldg(Pr + (size_t)md.x * 32 + lane);
        EDGE_PROC(md, pv);
    }

    uint2 o;
    o.x = *reinterpret_cast<uint32_t*>(&m0);
    o.y = *reinterpret_cast<uint32_t*>(&m1);
    poolb[(size_t)s * 32 + lane] = o;
}

// ---------------------------------------------------------------------------
extern "C" void kernel_launch(void* const* d_in, const int* in_sizes, int n_in,
                              void* d_out, int out_size)
{
    const float* interp = (const float*)d_in[0];
    const float* add    = (const float*)d_in[1];
    const int*   nidx   = (const int*)d_in[2];
    const int*   segs   = (const int*)d_in[3];
    const float* Wb0 = (const float*)d_in[4];
    const float* bb0 = (const float*)d_in[5];
    const float* Wo0 = (const float*)d_in[6];
    const float* bo0 = (const float*)d_in[7];
    const float* Wb1 = (const float*)d_in[8];
    const float* bb1 = (const float*)d_in[9];
    const float* Wo1 = (const float*)d_in[10];
    const float* bo1 = (const float*)d_in[11];
    const float* Wf  = (const float*)d_in[12];
    const float* bf  = (const float*)d_in[13];
    float* out = (float*)d_out;

    int N = in_sizes[0] / 128;
    int E = in_sizes[2];

    __nv_bfloat16 *P, *poolb, *Wt;
    float *x1;
    uint4* em;
    int* start;
    cudaGetSymbolAddress((void**)&P, g_P);
    cudaGetSymbolAddress((void**)&poolb, g_poolb);
    cudaGetSymbolAddress((void**)&x1, g_x1);
    cudaGetSymbolAddress((void**)&Wt, g_Wt);
    cudaGetSymbolAddress((void**)&em, g_edge);
    cudaGetSymbolAddress((void**)&start, g_start);

    cudaFuncSetAttribute(gemm_pre, cudaFuncAttributeMaxDynamicSharedMemorySize, SMEM_PF);
    cudaFuncSetAttribute(gemm_mid, cudaFuncAttributeMaxDynamicSharedMemorySize, SMEM_MID);
    cudaFuncSetAttribute(gemm_fin, cudaFuncAttributeMaxDynamicSharedMemorySize, SMEM_PF);

    int gtiles = (N + 63) / 64;
    int sgrid = (N + 7) / 8;

    prep_w<<<dim3(64, 4), 256>>>(Wb0, Wo0, Wb1, Wo1, Wt);
    prep_edge<<<(E + 255) / 256, 256>>>(segs, nidx, (const float4*)add, em,
                                        start, E, N);

    // Block 0
    gemm_pre<<<gtiles, 256, SMEM_PF>>>(interp, Wt + 0 * 16384, bb0, P, N);
    edge_kernel<<<sgrid, 256>>>((const uint2*)P, em, start, Wb0 + 128 * 128,
                                (uint2*)poolb, N);
    // Block-0 projection + Block-1 pre-edge GEMM fused
    gemm_mid<<<gtiles, 256, SMEM_MID>>>(poolb, Wt + 1 * 16384, bo0, interp, x1,
                                        Wt + 2 * 16384, bb1, P, N);
    edge_kernel<<<sgrid, 256>>>((const uint2*)P, em, start, Wb1 + 128 * 128,
                                (uint2*)poolb, N);
    // Block-1 projection + final head fused
    gemm_fin<<<gtiles, 256, SMEM_PF>>>(poolb, Wt + 3 * 16384, bo1, x1, Wf, bf,
                                       out, N);
}